// round 8
// baseline (speedup 1.0000x reference)
#include <cuda_runtime.h>
#include <cuda_bf16.h>
#include <math.h>
#include <stdint.h>

// ---------------- problem constants ----------------
#define B_   2
#define S_   4096
#define DM_  768
#define DI_  1152
#define H_   12
#define DH_  64
#define ROWS (B_ * S_)          // 8192
#define DQKV (3 * DM_)          // 2304
#define WIN  64                 // WINDOW/2

// ---------------- scratch ----------------
__device__ float g_h[ROWS * DM_];
__device__ float g_qkv[ROWS * DQKV];
__device__ float g_attn[ROWS * DM_];
__device__ float g_x1[ROWS * DM_];
__device__ float g_gate[ROWS * DI_];
__device__ float g_act[ROWS * DI_];
// tf32-rounded weights
__device__ float g_wqkv[DM_ * DQKV];
__device__ float g_wo  [DM_ * DM_];
__device__ float g_wi0 [DM_ * DI_];
__device__ float g_wi1 [DM_ * DI_];
__device__ float g_wmo [DI_ * DM_];

// ---------------- TF32 rounding ----------------
__device__ __forceinline__ float tf32r(float x) {
    uint32_t u;
    asm("cvt.rna.tf32.f32 %0, %1;" : "=r"(u) : "f"(x));
    return __uint_as_float(u);
}

__device__ __forceinline__ float warpSum(float v) {
    #pragma unroll
    for (int o = 16; o; o >>= 1) v += __shfl_xor_sync(0xffffffffu, v, o);
    return v;
}

// ---------------- weight pre-rounding (float4) ----------------
__global__ void tf32cvt4_kernel(const float4* __restrict__ in, float4* __restrict__ out, int n4) {
    int i = blockIdx.x * blockDim.x + threadIdx.x;
    if (i >= n4) return;
    float4 v = in[i];
    v.x = tf32r(v.x); v.y = tf32r(v.y); v.z = tf32r(v.z); v.w = tf32r(v.w);
    out[i] = v;
}

// ---------------- RMSNorm (tf32-rounded output; feeds GEMM-A only) ----------
__global__ void rmsnorm_kernel(const float* __restrict__ x,
                               const float* __restrict__ gamma,
                               float* __restrict__ o) {
    int row = blockIdx.x;
    const float* xr = x + (size_t)row * DM_;
    float s = 0.f;
    for (int i = threadIdx.x; i < DM_; i += 256) { float v = xr[i]; s += v * v; }
    __shared__ float red[8];
    float w = warpSum(s);
    if ((threadIdx.x & 31) == 0) red[threadIdx.x >> 5] = w;
    __syncthreads();
    float tot = 0.f;
    #pragma unroll
    for (int i = 0; i < 8; i++) tot += red[i];
    float inv = rsqrtf(tot / (float)DM_ + 1e-5f);
    float* orow = o + (size_t)row * DM_;
    for (int i = threadIdx.x; i < DM_; i += 256) orow[i] = tf32r(xr[i] * inv * gamma[i]);
}

// =================== TF32 tensor-core GEMM: 256x128x32, warp tile 64x64 =====
// mode 0: C = acc ; mode 1: C = Res + acc ; mode 2: C = tf32r(gelu(Res) * acc)
#define BM 256
#define BN 128
#define BK 32
#define ASTRIDE 36
#define BSTRIDE 136
#define STAGE_FLOATS (BM * ASTRIDE + BK * BSTRIDE)   // 13568
#define GEMM_SMEM_BYTES (2 * STAGE_FLOATS * 4)        // 108544

__device__ __forceinline__ void mma_tf32(float c[4], const uint32_t a[4], const uint32_t b[2]) {
    asm volatile(
        "mma.sync.aligned.m16n8k8.row.col.f32.tf32.tf32.f32 "
        "{%0,%1,%2,%3}, {%4,%5,%6,%7}, {%8,%9}, {%0,%1,%2,%3};"
        : "+f"(c[0]), "+f"(c[1]), "+f"(c[2]), "+f"(c[3])
        : "r"(a[0]), "r"(a[1]), "r"(a[2]), "r"(a[3]), "r"(b[0]), "r"(b[1]));
}

__device__ __forceinline__ void cp16(float* dst_smem, const float* src) {
    uint32_t d = (uint32_t)__cvta_generic_to_shared(dst_smem);
    asm volatile("cp.async.cg.shared.global [%0], [%1], 16;" :: "r"(d), "l"(src));
}

__device__ __forceinline__ float gelu_t(float x) {
    float t = tanhf(0.7978845608028654f * (x + 0.044715f * x * x * x));
    return 0.5f * x * (1.0f + t);
}

__global__ __launch_bounds__(256, 1)
void mma_gemm_kernel(const float* __restrict__ A, const float* __restrict__ Bg,
                     const float* __restrict__ Res, float* __restrict__ C,
                     int M, int N, int K, int mode) {
    extern __shared__ float smem[];
    float* stage[2] = { smem, smem + STAGE_FLOATS };

    const int tid  = threadIdx.x;
    const int lane = tid & 31;
    const int warp = tid >> 5;
    const int gid  = lane >> 2;   // 0..7
    const int tg   = lane & 3;    // 0..3
    const int wm   = warp >> 1;   // 0..3 -> m offset * 64
    const int wn   = warp & 1;    // 0..1 -> n offset * 64

    const int bm = blockIdx.y * BM;
    const int bn = blockIdx.x * BN;

    float acc[4][8][4];
    #pragma unroll
    for (int i = 0; i < 4; i++)
        #pragma unroll
        for (int j = 0; j < 8; j++)
            #pragma unroll
            for (int l = 0; l < 4; l++) acc[i][j][l] = 0.f;

    const int ntiles = K / BK;

    // stage tile t into buffer buf:
    //   A: 256x32 floats = 2048 float4 (8 per thread)
    //   B:  32x128 floats = 1024 float4 (4 per thread)
    #define ISSUE_TILE(t, buf) do {                                             \
        float* As_ = stage[buf];                                                \
        float* Bs_ = stage[buf] + BM * ASTRIDE;                                 \
        int k0_ = (t) * BK;                                                     \
        _Pragma("unroll")                                                       \
        for (int u = 0; u < 8; u++) {                                           \
            int i = tid + u * 256;                                              \
            int r = i >> 3, c4 = (i & 7) * 4;                                   \
            cp16(&As_[r * ASTRIDE + c4],                                        \
                 &A[(size_t)(bm + r) * K + k0_ + c4]);                          \
        }                                                                       \
        _Pragma("unroll")                                                       \
        for (int u = 0; u < 4; u++) {                                           \
            int i = tid + u * 256;                                              \
            int r = i >> 5, c4 = (i & 31) * 4;                                  \
            cp16(&Bs_[r * BSTRIDE + c4],                                        \
                 &Bg[(size_t)(k0_ + r) * N + bn + c4]);                         \
        }                                                                       \
        asm volatile("cp.async.commit_group;");                                 \
    } while (0)

    ISSUE_TILE(0, 0);

    for (int t = 0; t < ntiles; t++) {
        if (t + 1 < ntiles) {
            ISSUE_TILE(t + 1, (t + 1) & 1);
            asm volatile("cp.async.wait_group 1;");
        } else {
            asm volatile("cp.async.wait_group 0;");
        }
        __syncthreads();

        const float* As = stage[t & 1];
        const float* Bs = stage[t & 1] + BM * ASTRIDE;

        #pragma unroll
        for (int ks = 0; ks < 4; ks++) {
            uint32_t af[4][4], bf[8][2];
            int col = ks * 8 + tg;
            #pragma unroll
            for (int mt = 0; mt < 4; mt++) {
                int r = wm * 64 + mt * 16 + gid;
                af[mt][0] = __float_as_uint(As[r * ASTRIDE + col]);
                af[mt][1] = __float_as_uint(As[(r + 8) * ASTRIDE + col]);
                af[mt][2] = __float_as_uint(As[r * ASTRIDE + col + 4]);
                af[mt][3] = __float_as_uint(As[(r + 8) * ASTRIDE + col + 4]);
            }
            #pragma unroll
            for (int nt = 0; nt < 8; nt++) {
                int c = wn * 64 + nt * 8 + gid;
                bf[nt][0] = __float_as_uint(Bs[(ks * 8 + tg) * BSTRIDE + c]);
                bf[nt][1] = __float_as_uint(Bs[(ks * 8 + tg + 4) * BSTRIDE + c]);
            }
            #pragma unroll
            for (int mt = 0; mt < 4; mt++)
                #pragma unroll
                for (int nt = 0; nt < 8; nt++)
                    mma_tf32(acc[mt][nt], af[mt], bf[nt]);
        }
        __syncthreads();
    }

    #pragma unroll
    for (int mt = 0; mt < 4; mt++) {
        #pragma unroll
        for (int nt = 0; nt < 8; nt++) {
            int m0 = bm + wm * 64 + mt * 16 + gid;
            int n0 = bn + wn * 64 + nt * 8 + tg * 2;
            float2 v0 = make_float2(acc[mt][nt][0], acc[mt][nt][1]);
            float2 v1 = make_float2(acc[mt][nt][2], acc[mt][nt][3]);
            if (mode == 1) {
                float2 r0 = *(const float2*)&Res[(size_t)m0 * N + n0];
                float2 r1 = *(const float2*)&Res[(size_t)(m0 + 8) * N + n0];
                v0.x += r0.x; v0.y += r0.y;
                v1.x += r1.x; v1.y += r1.y;
            } else if (mode == 2) {
                float2 r0 = *(const float2*)&Res[(size_t)m0 * N + n0];
                float2 r1 = *(const float2*)&Res[(size_t)(m0 + 8) * N + n0];
                v0.x = tf32r(gelu_t(r0.x) * v0.x);
                v0.y = tf32r(gelu_t(r0.y) * v0.y);
                v1.x = tf32r(gelu_t(r1.x) * v1.x);
                v1.y = tf32r(gelu_t(r1.y) * v1.y);
            }
            *(float2*)&C[(size_t)m0 * N + n0] = v0;
            *(float2*)&C[(size_t)(m0 + 8) * N + n0] = v1;
        }
    }
}

// =================== tiled sliding-window attention (R6, unchanged) ====
#define QT 64
#define KT 192
#define SSTR 196
#define ATTN_Q_FLOATS   (QT * DH_)
#define ATTN_K_FLOATS   (KT * DH_)
#define ATTN_S_FLOATS   (QT * SSTR)
#define ATTN_SMEM_FLOATS (ATTN_Q_FLOATS + 2 * ATTN_K_FLOATS + ATTN_S_FLOATS)
#define ATTN_SMEM_BYTES  (ATTN_SMEM_FLOATS * 4)

__device__ __forceinline__ int ksw(int row, int chunk) {
    return row * DH_ + 4 * (chunk ^ ((row >> 2) & 15));
}

__device__ __forceinline__ void rope4(int s, int c, float4& lo, float4& hi) {
    #pragma unroll
    for (int l = 0; l < 4; l++) {
        int d = c * 4 + l;
        float w = (float)(2 * d) / (float)DH_;
        float inv_freq = 1.0f / powf(10000.0f, w);
        float ang = (float)s * inv_freq;
        float cs = cosf(ang);
        float sn = sinf(ang);
        float x1 = (&lo.x)[l];
        float x2 = (&hi.x)[l];
        (&lo.x)[l] = tf32r(x1 * cs - x2 * sn);
        (&hi.x)[l] = tf32r(x2 * cs + x1 * sn);
    }
}

__global__ __launch_bounds__(512, 1)
void attn_tile_kernel(const float* __restrict__ qkv, const int* __restrict__ pmask,
                      float* __restrict__ out) {
    extern __shared__ float sm[];
    float* Qs = sm;
    float* Ks = Qs + ATTN_Q_FLOATS;
    float* Vs = Ks + ATTN_K_FLOATS;
    float* Sc = Vs + ATTN_K_FLOATS;

    const int qt0 = blockIdx.x * QT;
    const int h   = blockIdx.y;
    const int b   = blockIdx.z;
    const int tid = threadIdx.x;

    {
        int r = tid >> 3, c = tid & 7;
        int s = qt0 + r;
        size_t base = (size_t)(b * S_ + s) * DQKV + h * DH_;
        float4 lo = *(const float4*)&qkv[base + c * 4];
        float4 hi = *(const float4*)&qkv[base + 32 + c * 4];
        rope4(s, c, lo, hi);
        *(float4*)&Qs[r * DH_ + c * 4] = lo;
        *(float4*)&Qs[r * DH_ + 32 + c * 4] = hi;
    }
    for (int i = tid; i < KT * 8; i += 512) {
        int r = i >> 3, c = i & 7;
        int j = qt0 - WIN + r;
        float4 klo = make_float4(0.f,0.f,0.f,0.f), khi = klo, vlo = klo, vhi = klo;
        if (j >= 0 && j < S_) {
            size_t base = (size_t)(b * S_ + j) * DQKV + h * DH_;
            klo = *(const float4*)&qkv[base + DM_ + c * 4];
            khi = *(const float4*)&qkv[base + DM_ + 32 + c * 4];
            rope4(j, c, klo, khi);
            vlo = *(const float4*)&qkv[base + 2 * DM_ + c * 4];
            vhi = *(const float4*)&qkv[base + 2 * DM_ + 32 + c * 4];
            vlo.x = tf32r(vlo.x); vlo.y = tf32r(vlo.y); vlo.z = tf32r(vlo.z); vlo.w = tf32r(vlo.w);
            vhi.x = tf32r(vhi.x); vhi.y = tf32r(vhi.y); vhi.z = tf32r(vhi.z); vhi.w = tf32r(vhi.w);
        }
        *(float4*)&Ks[ksw(r, c)] = klo;
        *(float4*)&Ks[ksw(r, c + 8)] = khi;
        *(float4*)&Vs[r * DH_ + c * 4] = vlo;
        *(float4*)&Vs[r * DH_ + 32 + c * 4] = vhi;
    }
    __syncthreads();

    {
        const int tk = tid & 15;
        const int tq = tid >> 4;
        #pragma unroll
        for (int kp = 0; kp < 3; kp++) {
            const int kbase = kp * 64 + tk * 4;
            float acc[2][4];
            #pragma unroll
            for (int i = 0; i < 2; i++)
                #pragma unroll
                for (int u = 0; u < 4; u++) acc[i][u] = 0.f;

            for (int c = 0; c < 16; c++) {
                float4 qv[2], kv[4];
                #pragma unroll
                for (int i = 0; i < 2; i++)
                    qv[i] = *(const float4*)&Qs[(tq * 2 + i) * DH_ + c * 4];
                #pragma unroll
                for (int u = 0; u < 4; u++)
                    kv[u] = *(const float4*)&Ks[ksw(kbase + u, c)];
                #pragma unroll
                for (int i = 0; i < 2; i++)
                    #pragma unroll
                    for (int u = 0; u < 4; u++)
                        acc[i][u] += qv[i].x * kv[u].x + qv[i].y * kv[u].y
                                   + qv[i].z * kv[u].z + qv[i].w * kv[u].w;
            }
            #pragma unroll
            for (int i = 0; i < 2; i++) {
                int ql = tq * 2 + i;
                int qg = qt0 + ql;
                #pragma unroll
                for (int u = 0; u < 4; u++) {
                    int kr = kbase + u;
                    int j = qt0 - WIN + kr;
                    float s;
                    if (j < 0 || j >= S_) {
                        s = -1e30f;
                    } else {
                        s = acc[i][u] * 0.125f;
                        int diff = j - qg;
                        if (diff > WIN || diff < -WIN) s -= 10000.0f;
                        if (pmask[b * S_ + j] == 0)    s -= 10000.0f;
                    }
                    Sc[ql * SSTR + kr] = s;
                }
            }
        }
    }
    __syncthreads();

    {
        const int row = tid >> 3, sub = tid & 7;
        float m = -1e30f;
        for (int k = sub; k < KT; k += 8) m = fmaxf(m, Sc[row * SSTR + k]);
        m = fmaxf(m, __shfl_xor_sync(0xffffffffu, m, 1));
        m = fmaxf(m, __shfl_xor_sync(0xffffffffu, m, 2));
        m = fmaxf(m, __shfl_xor_sync(0xffffffffu, m, 4));
        float ssum = 0.f;
        for (int k = sub; k < KT; k += 8) {
            float e = expf(Sc[row * SSTR + k] - m);
            Sc[row * SSTR + k] = e;
            ssum += e;
        }
        ssum += __shfl_xor_sync(0xffffffffu, ssum, 1);
        ssum += __shfl_xor_sync(0xffffffffu, ssum, 2);
        ssum += __shfl_xor_sync(0xffffffffu, ssum, 4);
        for (int k = sub; k < KT; k += 8)
            Sc[row * SSTR + k] = tf32r(Sc[row * SSTR + k] / ssum);
    }
    __syncthreads();

    {
        const int d4 = (tid & 15) * 4;
        const int q2 = (tid >> 4) * 2;
        float o[2][4];
        #pragma unroll
        for (int i = 0; i < 2; i++)
            #pragma unroll
            for (int u = 0; u < 4; u++) o[i][u] = 0.f;

        for (int k = 0; k < KT; k += 4) {
            float4 pv[2];
            #pragma unroll
            for (int i = 0; i < 2; i++)
                pv[i] = *(const float4*)&Sc[(q2 + i) * SSTR + k];
            #pragma unroll
            for (int kk = 0; kk < 4; kk++) {
                float4 vv = *(const float4*)&Vs[(k + kk) * DH_ + d4];
                #pragma unroll
                for (int i = 0; i < 2; i++) {
                    float p = (kk == 0) ? pv[i].x : (kk == 1) ? pv[i].y : (kk == 2) ? pv[i].z : pv[i].w;
                    o[i][0] += p * vv.x;
                    o[i][1] += p * vv.y;
                    o[i][2] += p * vv.z;
                    o[i][3] += p * vv.w;
                }
            }
        }
        #pragma unroll
        for (int i = 0; i < 2; i++) {
            float4 v = make_float4(tf32r(o[i][0]), tf32r(o[i][1]), tf32r(o[i][2]), tf32r(o[i][3]));
            *(float4*)&out[(size_t)(b * S_ + qt0 + q2 + i) * DM_ + h * DH_ + d4] = v;
        }
    }
}

// ---------------- launch ----------------
extern "C" void kernel_launch(void* const* d_in, const int* in_sizes, int n_in,
                              void* d_out, int out_size) {
    const float* x          = (const float*)d_in[0];
    const int*   pmask      = (const int*)  d_in[1];
    const float* w_qkv      = (const float*)d_in[2];
    const float* w_o        = (const float*)d_in[3];
    const float* gamma_attn = (const float*)d_in[4];
    const float* gamma_mlp  = (const float*)d_in[5];
    const float* w_i0       = (const float*)d_in[6];
    const float* w_i1       = (const float*)d_in[7];
    const float* w_mo       = (const float*)d_in[8];
    float* out = (float*)d_out;

    float *h, *qkv, *attn, *x1, *gate, *act;
    float *wqkv, *wo, *wi0, *wi1, *wmo;
    cudaGetSymbolAddress((void**)&h,    g_h);
    cudaGetSymbolAddress((void**)&qkv,  g_qkv);
    cudaGetSymbolAddress((void**)&attn, g_attn);
    cudaGetSymbolAddress((void**)&x1,   g_x1);
    cudaGetSymbolAddress((void**)&gate, g_gate);
    cudaGetSymbolAddress((void**)&act,  g_act);
    cudaGetSymbolAddress((void**)&wqkv, g_wqkv);
    cudaGetSymbolAddress((void**)&wo,   g_wo);
    cudaGetSymbolAddress((void**)&wi0,  g_wi0);
    cudaGetSymbolAddress((void**)&wi1,  g_wi1);
    cudaGetSymbolAddress((void**)&wmo,  g_wmo);

    cudaFuncSetAttribute(mma_gemm_kernel,
                         cudaFuncAttributeMaxDynamicSharedMemorySize, GEMM_SMEM_BYTES);
    cudaFuncSetAttribute(attn_tile_kernel,
                         cudaFuncAttributeMaxDynamicSharedMemorySize, ATTN_SMEM_BYTES);

    tf32cvt4_kernel<<<(DM_ * DQKV / 4 + 255) / 256, 256>>>((const float4*)w_qkv, (float4*)wqkv, DM_ * DQKV / 4);
    tf32cvt4_kernel<<<(DM_ * DM_  / 4 + 255) / 256, 256>>>((const float4*)w_o,   (float4*)wo,   DM_ * DM_  / 4);
    tf32cvt4_kernel<<<(DM_ * DI_  / 4 + 255) / 256, 256>>>((const float4*)w_i0,  (float4*)wi0,  DM_ * DI_  / 4);
    tf32cvt4_kernel<<<(DM_ * DI_  / 4 + 255) / 256, 256>>>((const float4*)w_i1,  (float4*)wi1,  DM_ * DI_  / 4);
    tf32cvt4_kernel<<<(DI_ * DM_  / 4 + 255) / 256, 256>>>((const float4*)w_mo,  (float4*)wmo,  DI_ * DM_  / 4);

    rmsnorm_kernel<<<ROWS, 256>>>(x, gamma_attn, h);
    mma_gemm_kernel<<<dim3(DQKV / BN, ROWS / BM), 256, GEMM_SMEM_BYTES>>>(
        h, wqkv, nullptr, qkv, ROWS, DQKV, DM_, 0);
    attn_tile_kernel<<<dim3(S_ / QT, H_, B_), 512, ATTN_SMEM_BYTES>>>(qkv, pmask, attn);
    mma_gemm_kernel<<<dim3(DM_ / BN, ROWS / BM), 256, GEMM_SMEM_BYTES>>>(
        attn, wo, x, x1, ROWS, DM_, DM_, 1);
    rmsnorm_kernel<<<ROWS, 256>>>(x1, gamma_mlp, h);
    mma_gemm_kernel<<<dim3(DI_ / BN, ROWS / BM), 256, GEMM_SMEM_BYTES>>>(
        h, wi0, nullptr, gate, ROWS, DI_, DM_, 0);
    mma_gemm_kernel<<<dim3(DI_ / BN, ROWS / BM), 256, GEMM_SMEM_BYTES>>>(
        h, wi1, gate, act, ROWS, DI_, DM_, 2);
    mma_gemm_kernel<<<dim3(DM_ / BN, ROWS / BM), 256, GEMM_SMEM_BYTES>>>(
        act, wmo, x1, out, ROWS, DM_, DI_, 1);
}

// round 9
// speedup vs baseline: 1.1860x; 1.1860x over previous
#include <cuda_runtime.h>
#include <cuda_bf16.h>
#include <math.h>
#include <stdint.h>

// ---------------- problem constants ----------------
#define B_   2
#define S_   4096
#define DM_  768
#define DI_  1152
#define H_   12
#define DH_  64
#define ROWS (B_ * S_)          // 8192
#define DQKV (3 * DM_)          // 2304
#define WIN  64                 // WINDOW/2

// ---------------- scratch ----------------
__device__ float g_h[ROWS * DM_];
__device__ float g_qkv[ROWS * DQKV];
__device__ float g_attn[ROWS * DM_];
__device__ float g_x1[ROWS * DM_];
__device__ float g_gate[ROWS * DI_];
__device__ float g_act[ROWS * DI_];
__device__ float2 g_rope[S_ * 32];   // cos/sin table
// tf32-rounded weights
__device__ float g_wqkv[DM_ * DQKV];
__device__ float g_wo  [DM_ * DM_];
__device__ float g_wi0 [DM_ * DI_];
__device__ float g_wi1 [DM_ * DI_];
__device__ float g_wmo [DI_ * DM_];

// ---------------- TF32 rounding ----------------
__device__ __forceinline__ float tf32r(float x) {
    uint32_t u;
    asm("cvt.rna.tf32.f32 %0, %1;" : "=r"(u) : "f"(x));
    return __uint_as_float(u);
}

__device__ __forceinline__ float warpSum(float v) {
    #pragma unroll
    for (int o = 16; o; o >>= 1) v += __shfl_xor_sync(0xffffffffu, v, o);
    return v;
}

// ---------------- weight pre-rounding (float4) ----------------
__global__ void tf32cvt4_kernel(const float4* __restrict__ in, float4* __restrict__ out, int n4) {
    int i = blockIdx.x * blockDim.x + threadIdx.x;
    if (i >= n4) return;
    float4 v = in[i];
    v.x = tf32r(v.x); v.y = tf32r(v.y); v.z = tf32r(v.z); v.w = tf32r(v.w);
    out[i] = v;
}

// ---------------- RoPE table (identical math to reference path) ------------
__global__ void ropetab_kernel(float2* __restrict__ tab) {
    int idx = blockIdx.x * blockDim.x + threadIdx.x;
    if (idx >= S_ * 32) return;
    int s = idx >> 5, d = idx & 31;
    float w = (float)(2 * d) / (float)DH_;
    float inv_freq = 1.0f / powf(10000.0f, w);
    float ang = (float)s * inv_freq;
    tab[idx] = make_float2(cosf(ang), sinf(ang));
}

// ---------------- RMSNorm (tf32-rounded output; feeds GEMM-A only) ----------
__global__ void rmsnorm_kernel(const float* __restrict__ x,
                               const float* __restrict__ gamma,
                               float* __restrict__ o) {
    int row = blockIdx.x;
    const float* xr = x + (size_t)row * DM_;
    float s = 0.f;
    for (int i = threadIdx.x; i < DM_; i += 256) { float v = xr[i]; s += v * v; }
    __shared__ float red[8];
    float w = warpSum(s);
    if ((threadIdx.x & 31) == 0) red[threadIdx.x >> 5] = w;
    __syncthreads();
    float tot = 0.f;
    #pragma unroll
    for (int i = 0; i < 8; i++) tot += red[i];
    float inv = rsqrtf(tot / (float)DM_ + 1e-5f);
    float* orow = o + (size_t)row * DM_;
    for (int i = threadIdx.x; i < DM_; i += 256) orow[i] = tf32r(xr[i] * inv * gamma[i]);
}

// =================== TF32 tensor-core GEMM: 128x128x32, 3-stage cp.async ====
// mode 0: C = acc ; mode 1: C = Res + acc ; mode 2: C = tf32r(gelu(Res) * acc)
#define BM 128
#define BN 128
#define BK 32
#define ASTRIDE 36
#define BSTRIDE 136
#define STAGE_FLOATS (BM * ASTRIDE + BK * BSTRIDE)   // 8960
#define NSTAGE 3
#define GEMM_SMEM_BYTES (NSTAGE * STAGE_FLOATS * 4)  // 107520

__device__ __forceinline__ void mma_tf32(float c[4], const uint32_t a[4], const uint32_t b[2]) {
    asm volatile(
        "mma.sync.aligned.m16n8k8.row.col.f32.tf32.tf32.f32 "
        "{%0,%1,%2,%3}, {%4,%5,%6,%7}, {%8,%9}, {%0,%1,%2,%3};"
        : "+f"(c[0]), "+f"(c[1]), "+f"(c[2]), "+f"(c[3])
        : "r"(a[0]), "r"(a[1]), "r"(a[2]), "r"(a[3]), "r"(b[0]), "r"(b[1]));
}

__device__ __forceinline__ void cp16(float* dst_smem, const float* src) {
    uint32_t d = (uint32_t)__cvta_generic_to_shared(dst_smem);
    asm volatile("cp.async.cg.shared.global [%0], [%1], 16;" :: "r"(d), "l"(src));
}

__device__ __forceinline__ float gelu_t(float x) {
    float t = tanhf(0.7978845608028654f * (x + 0.044715f * x * x * x));
    return 0.5f * x * (1.0f + t);
}

__global__ __launch_bounds__(256, 2)
void mma_gemm_kernel(const float* __restrict__ A, const float* __restrict__ Bg,
                     const float* __restrict__ Res, float* __restrict__ C,
                     int M, int N, int K, int mode) {
    extern __shared__ float smem[];

    const int tid  = threadIdx.x;
    const int lane = tid & 31;
    const int warp = tid >> 5;
    const int gid  = lane >> 2;
    const int tg   = lane & 3;
    const int wm   = warp >> 1;
    const int wn   = warp & 1;

    const int bm = blockIdx.y * BM;
    const int bn = blockIdx.x * BN;

    const int arow = tid >> 3;
    const int acol = (tid & 7) * 4;
    const int brow = tid >> 5;
    const int bcol = (tid & 31) * 4;

    float acc[2][8][4];
    #pragma unroll
    for (int i = 0; i < 2; i++)
        #pragma unroll
        for (int j = 0; j < 8; j++)
            #pragma unroll
            for (int l = 0; l < 4; l++) acc[i][j][l] = 0.f;

    const int ntiles = K / BK;

    #define ISSUE_TILE(t, buf) do {                                            \
        float* As_ = smem + (buf) * STAGE_FLOATS;                               \
        float* Bs_ = As_ + BM * ASTRIDE;                                        \
        int k0_ = (t) * BK;                                                     \
        _Pragma("unroll")                                                       \
        for (int i = 0; i < 4; i++)                                             \
            cp16(&As_[(arow + 32 * i) * ASTRIDE + acol],                        \
                 &A[(size_t)(bm + arow + 32 * i) * K + k0_ + acol]);            \
        _Pragma("unroll")                                                       \
        for (int i = 0; i < 4; i++)                                             \
            cp16(&Bs_[(brow + 8 * i) * BSTRIDE + bcol],                         \
                 &Bg[(size_t)(k0_ + brow + 8 * i) * N + bn + bcol]);            \
        asm volatile("cp.async.commit_group;");                                 \
    } while (0)

    ISSUE_TILE(0, 0);
    if (ntiles > 1) ISSUE_TILE(1, 1);

    int buf = 0;
    for (int t = 0; t < ntiles; t++) {
        if (t + 1 < ntiles) {
            asm volatile("cp.async.wait_group 1;");
        } else {
            asm volatile("cp.async.wait_group 0;");
        }
        __syncthreads();

        // prefetch tile t+2 into buffer (t+2)%3 (safe: all warps done reading it)
        if (t + 2 < ntiles) {
            int nb = buf + 2; if (nb >= NSTAGE) nb -= NSTAGE;
            ISSUE_TILE(t + 2, nb);
        }

        const float* As = smem + buf * STAGE_FLOATS;
        const float* Bs = As + BM * ASTRIDE;

        #pragma unroll
        for (int ks = 0; ks < 4; ks++) {
            uint32_t af[2][4], bf[8][2];
            int col = ks * 8 + tg;
            #pragma unroll
            for (int mt = 0; mt < 2; mt++) {
                int r = wm * 32 + mt * 16 + gid;
                af[mt][0] = __float_as_uint(As[r * ASTRIDE + col]);
                af[mt][1] = __float_as_uint(As[(r + 8) * ASTRIDE + col]);
                af[mt][2] = __float_as_uint(As[r * ASTRIDE + col + 4]);
                af[mt][3] = __float_as_uint(As[(r + 8) * ASTRIDE + col + 4]);
            }
            #pragma unroll
            for (int nt = 0; nt < 8; nt++) {
                int c = wn * 64 + nt * 8 + gid;
                bf[nt][0] = __float_as_uint(Bs[(ks * 8 + tg) * BSTRIDE + c]);
                bf[nt][1] = __float_as_uint(Bs[(ks * 8 + tg + 4) * BSTRIDE + c]);
            }
            #pragma unroll
            for (int mt = 0; mt < 2; mt++)
                #pragma unroll
                for (int nt = 0; nt < 8; nt++)
                    mma_tf32(acc[mt][nt], af[mt], bf[nt]);
        }

        buf++; if (buf >= NSTAGE) buf = 0;
    }

    #pragma unroll
    for (int mt = 0; mt < 2; mt++) {
        #pragma unroll
        for (int nt = 0; nt < 8; nt++) {
            int m0 = bm + wm * 32 + mt * 16 + gid;
            int n0 = bn + wn * 64 + nt * 8 + tg * 2;
            float2 v0 = make_float2(acc[mt][nt][0], acc[mt][nt][1]);
            float2 v1 = make_float2(acc[mt][nt][2], acc[mt][nt][3]);
            if (mode == 1) {
                float2 r0 = *(const float2*)&Res[(size_t)m0 * N + n0];
                float2 r1 = *(const float2*)&Res[(size_t)(m0 + 8) * N + n0];
                v0.x += r0.x; v0.y += r0.y;
                v1.x += r1.x; v1.y += r1.y;
            } else if (mode == 2) {
                float2 r0 = *(const float2*)&Res[(size_t)m0 * N + n0];
                float2 r1 = *(const float2*)&Res[(size_t)(m0 + 8) * N + n0];
                v0.x = tf32r(gelu_t(r0.x) * v0.x);
                v0.y = tf32r(gelu_t(r0.y) * v0.y);
                v1.x = tf32r(gelu_t(r1.x) * v1.x);
                v1.y = tf32r(gelu_t(r1.y) * v1.y);
            }
            *(float2*)&C[(size_t)m0 * N + n0] = v0;
            *(float2*)&C[(size_t)(m0 + 8) * N + n0] = v1;
        }
    }
}

// =================== tiled sliding-window attention (rope table) ====
#define QT 64
#define KT 192
#define SSTR 196
#define ATTN_Q_FLOATS   (QT * DH_)
#define ATTN_K_FLOATS   (KT * DH_)
#define ATTN_S_FLOATS   (QT * SSTR)
#define ATTN_SMEM_FLOATS (ATTN_Q_FLOATS + 2 * ATTN_K_FLOATS + ATTN_S_FLOATS)
#define ATTN_SMEM_BYTES  (ATTN_SMEM_FLOATS * 4)

__device__ __forceinline__ int ksw(int row, int chunk) {
    return row * DH_ + 4 * (chunk ^ ((row >> 2) & 15));
}

__device__ __forceinline__ void rope4t(const float2* __restrict__ tab, int s, int c,
                                       float4& lo, float4& hi) {
    #pragma unroll
    for (int l = 0; l < 4; l++) {
        float2 cs = tab[s * 32 + c * 4 + l];
        float x1 = (&lo.x)[l];
        float x2 = (&hi.x)[l];
        (&lo.x)[l] = tf32r(x1 * cs.x - x2 * cs.y);
        (&hi.x)[l] = tf32r(x2 * cs.x + x1 * cs.y);
    }
}

__global__ __launch_bounds__(512, 1)
void attn_tile_kernel(const float* __restrict__ qkv, const int* __restrict__ pmask,
                      const float2* __restrict__ ropeT, float* __restrict__ out) {
    extern __shared__ float sm[];
    float* Qs = sm;
    float* Ks = Qs + ATTN_Q_FLOATS;
    float* Vs = Ks + ATTN_K_FLOATS;
    float* Sc = Vs + ATTN_K_FLOATS;

    const int qt0 = blockIdx.x * QT;
    const int h   = blockIdx.y;
    const int b   = blockIdx.z;
    const int tid = threadIdx.x;

    {
        int r = tid >> 3, c = tid & 7;
        int s = qt0 + r;
        size_t base = (size_t)(b * S_ + s) * DQKV + h * DH_;
        float4 lo = *(const float4*)&qkv[base + c * 4];
        float4 hi = *(const float4*)&qkv[base + 32 + c * 4];
        rope4t(ropeT, s, c, lo, hi);
        *(float4*)&Qs[r * DH_ + c * 4] = lo;
        *(float4*)&Qs[r * DH_ + 32 + c * 4] = hi;
    }
    for (int i = tid; i < KT * 8; i += 512) {
        int r = i >> 3, c = i & 7;
        int j = qt0 - WIN + r;
        float4 klo = make_float4(0.f,0.f,0.f,0.f), khi = klo, vlo = klo, vhi = klo;
        if (j >= 0 && j < S_) {
            size_t base = (size_t)(b * S_ + j) * DQKV + h * DH_;
            klo = *(const float4*)&qkv[base + DM_ + c * 4];
            khi = *(const float4*)&qkv[base + DM_ + 32 + c * 4];
            rope4t(ropeT, j, c, klo, khi);
            vlo = *(const float4*)&qkv[base + 2 * DM_ + c * 4];
            vhi = *(const float4*)&qkv[base + 2 * DM_ + 32 + c * 4];
            vlo.x = tf32r(vlo.x); vlo.y = tf32r(vlo.y); vlo.z = tf32r(vlo.z); vlo.w = tf32r(vlo.w);
            vhi.x = tf32r(vhi.x); vhi.y = tf32r(vhi.y); vhi.z = tf32r(vhi.z); vhi.w = tf32r(vhi.w);
        }
        *(float4*)&Ks[ksw(r, c)] = klo;
        *(float4*)&Ks[ksw(r, c + 8)] = khi;
        *(float4*)&Vs[r * DH_ + c * 4] = vlo;
        *(float4*)&Vs[r * DH_ + 32 + c * 4] = vhi;
    }
    __syncthreads();

    {
        const int tk = tid & 15;
        const int tq = tid >> 4;
        #pragma unroll
        for (int kp = 0; kp < 3; kp++) {
            const int kbase = kp * 64 + tk * 4;
            float acc[2][4];
            #pragma unroll
            for (int i = 0; i < 2; i++)
                #pragma unroll
                for (int u = 0; u < 4; u++) acc[i][u] = 0.f;

            for (int c = 0; c < 16; c++) {
                float4 qv[2], kv[4];
                #pragma unroll
                for (int i = 0; i < 2; i++)
                    qv[i] = *(const float4*)&Qs[(tq * 2 + i) * DH_ + c * 4];
                #pragma unroll
                for (int u = 0; u < 4; u++)
                    kv[u] = *(const float4*)&Ks[ksw(kbase + u, c)];
                #pragma unroll
                for (int i = 0; i < 2; i++)
                    #pragma unroll
                    for (int u = 0; u < 4; u++)
                        acc[i][u] += qv[i].x * kv[u].x + qv[i].y * kv[u].y
                                   + qv[i].z * kv[u].z + qv[i].w * kv[u].w;
            }
            #pragma unroll
            for (int i = 0; i < 2; i++) {
                int ql = tq * 2 + i;
                int qg = qt0 + ql;
                #pragma unroll
                for (int u = 0; u < 4; u++) {
                    int kr = kbase + u;
                    int j = qt0 - WIN + kr;
                    float s;
                    if (j < 0 || j >= S_) {
                        s = -1e30f;
                    } else {
                        s = acc[i][u] * 0.125f;
                        int diff = j - qg;
                        if (diff > WIN || diff < -WIN) s -= 10000.0f;
                        if (pmask[b * S_ + j] == 0)    s -= 10000.0f;
                    }
                    Sc[ql * SSTR + kr] = s;
                }
            }
        }
    }
    __syncthreads();

    {
        const int row = tid >> 3, sub = tid & 7;
        float m = -1e30f;
        for (int k = sub; k < KT; k += 8) m = fmaxf(m, Sc[row * SSTR + k]);
        m = fmaxf(m, __shfl_xor_sync(0xffffffffu, m, 1));
        m = fmaxf(m, __shfl_xor_sync(0xffffffffu, m, 2));
        m = fmaxf(m, __shfl_xor_sync(0xffffffffu, m, 4));
        float ssum = 0.f;
        for (int k = sub; k < KT; k += 8) {
            float e = expf(Sc[row * SSTR + k] - m);
            Sc[row * SSTR + k] = e;
            ssum += e;
        }
        ssum += __shfl_xor_sync(0xffffffffu, ssum, 1);
        ssum += __shfl_xor_sync(0xffffffffu, ssum, 2);
        ssum += __shfl_xor_sync(0xffffffffu, ssum, 4);
        for (int k = sub; k < KT; k += 8)
            Sc[row * SSTR + k] = tf32r(Sc[row * SSTR + k] / ssum);
    }
    __syncthreads();

    {
        const int d4 = (tid & 15) * 4;
        const int q2 = (tid >> 4) * 2;
        float o[2][4];
        #pragma unroll
        for (int i = 0; i < 2; i++)
            #pragma unroll
            for (int u = 0; u < 4; u++) o[i][u] = 0.f;

        for (int k = 0; k < KT; k += 4) {
            float4 pv[2];
            #pragma unroll
            for (int i = 0; i < 2; i++)
                pv[i] = *(const float4*)&Sc[(q2 + i) * SSTR + k];
            #pragma unroll
            for (int kk = 0; kk < 4; kk++) {
                float4 vv = *(const float4*)&Vs[(k + kk) * DH_ + d4];
                #pragma unroll
                for (int i = 0; i < 2; i++) {
                    float p = (kk == 0) ? pv[i].x : (kk == 1) ? pv[i].y : (kk == 2) ? pv[i].z : pv[i].w;
                    o[i][0] += p * vv.x;
                    o[i][1] += p * vv.y;
                    o[i][2] += p * vv.z;
                    o[i][3] += p * vv.w;
                }
            }
        }
        #pragma unroll
        for (int i = 0; i < 2; i++) {
            float4 v = make_float4(tf32r(o[i][0]), tf32r(o[i][1]), tf32r(o[i][2]), tf32r(o[i][3]));
            *(float4*)&out[(size_t)(b * S_ + qt0 + q2 + i) * DM_ + h * DH_ + d4] = v;
        }
    }
}

// ---------------- launch ----------------
extern "C" void kernel_launch(void* const* d_in, const int* in_sizes, int n_in,
                              void* d_out, int out_size) {
    const float* x          = (const float*)d_in[0];
    const int*   pmask      = (const int*)  d_in[1];
    const float* w_qkv      = (const float*)d_in[2];
    const float* w_o        = (const float*)d_in[3];
    const float* gamma_attn = (const float*)d_in[4];
    const float* gamma_mlp  = (const float*)d_in[5];
    const float* w_i0       = (const float*)d_in[6];
    const float* w_i1       = (const float*)d_in[7];
    const float* w_mo       = (const float*)d_in[8];
    float* out = (float*)d_out;

    float *h, *qkv, *attn, *x1, *gate, *act;
    float *wqkv, *wo, *wi0, *wi1, *wmo;
    float2* ropeT;
    cudaGetSymbolAddress((void**)&h,    g_h);
    cudaGetSymbolAddress((void**)&qkv,  g_qkv);
    cudaGetSymbolAddress((void**)&attn, g_attn);
    cudaGetSymbolAddress((void**)&x1,   g_x1);
    cudaGetSymbolAddress((void**)&gate, g_gate);
    cudaGetSymbolAddress((void**)&act,  g_act);
    cudaGetSymbolAddress((void**)&ropeT, g_rope);
    cudaGetSymbolAddress((void**)&wqkv, g_wqkv);
    cudaGetSymbolAddress((void**)&wo,   g_wo);
    cudaGetSymbolAddress((void**)&wi0,  g_wi0);
    cudaGetSymbolAddress((void**)&wi1,  g_wi1);
    cudaGetSymbolAddress((void**)&wmo,  g_wmo);

    cudaFuncSetAttribute(mma_gemm_kernel,
                         cudaFuncAttributeMaxDynamicSharedMemorySize, GEMM_SMEM_BYTES);
    cudaFuncSetAttribute(attn_tile_kernel,
                         cudaFuncAttributeMaxDynamicSharedMemorySize, ATTN_SMEM_BYTES);

    tf32cvt4_kernel<<<(DM_ * DQKV / 4 + 255) / 256, 256>>>((const float4*)w_qkv, (float4*)wqkv, DM_ * DQKV / 4);
    tf32cvt4_kernel<<<(DM_ * DM_  / 4 + 255) / 256, 256>>>((const float4*)w_o,   (float4*)wo,   DM_ * DM_  / 4);
    tf32cvt4_kernel<<<(DM_ * DI_  / 4 + 255) / 256, 256>>>((const float4*)w_i0,  (float4*)wi0,  DM_ * DI_  / 4);
    tf32cvt4_kernel<<<(DM_ * DI_  / 4 + 255) / 256, 256>>>((const float4*)w_i1,  (float4*)wi1,  DM_ * DI_  / 4);
    tf32cvt4_kernel<<<(DI_ * DM_  / 4 + 255) / 256, 256>>>((const float4*)w_mo,  (float4*)wmo,  DI_ * DM_  / 4);
    ropetab_kernel<<<(S_ * 32 + 255) / 256, 256>>>(ropeT);

    rmsnorm_kernel<<<ROWS, 256>>>(x, gamma_attn, h);
    mma_gemm_kernel<<<dim3(DQKV / BN, ROWS / BM), 256, GEMM_SMEM_BYTES>>>(
        h, wqkv, nullptr, qkv, ROWS, DQKV, DM_, 0);
    attn_tile_kernel<<<dim3(S_ / QT, H_, B_), 512, ATTN_SMEM_BYTES>>>(qkv, pmask, ropeT, attn);
    mma_gemm_kernel<<<dim3(DM_ / BN, ROWS / BM), 256, GEMM_SMEM_BYTES>>>(
        attn, wo, x, x1, ROWS, DM_, DM_, 1);
    rmsnorm_kernel<<<ROWS, 256>>>(x1, gamma_mlp, h);
    mma_gemm_kernel<<<dim3(DI_ / BN, ROWS / BM), 256, GEMM_SMEM_BYTES>>>(
        h, wi0, nullptr, gate, ROWS, DI_, DM_, 0);
    mma_gemm_kernel<<<dim3(DI_ / BN, ROWS / BM), 256, GEMM_SMEM_BYTES>>>(
        h, wi1, gate, act, ROWS, DI_, DM_, 2);
    mma_gemm_kernel<<<dim3(DM_ / BN, ROWS / BM), 256, GEMM_SMEM_BYTES>>>(
        act, wmo, x1, out, ROWS, DM_, DI_, 1);
}

// round 10
// speedup vs baseline: 1.5422x; 1.3003x over previous
#include <cuda_runtime.h>
#include <cuda_fp16.h>
#include <math.h>
#include <stdint.h>

// ---------------- problem constants ----------------
#define B_   2
#define S_   4096
#define DM_  768
#define DI_  1152
#define H_   12
#define DH_  64
#define ROWS (B_ * S_)          // 8192
#define DQKV (3 * DM_)          // 2304
#define WIN  64                 // WINDOW/2

// ---------------- scratch ----------------
__device__ __half g_h[ROWS * DM_];        // rmsnorm out (fp16, feeds GEMM-A)
__device__ float  g_qkv[ROWS * DQKV];     // qkv (fp32, feeds attention)
__device__ __half g_attn[ROWS * DM_];     // attention out (fp16)
__device__ float  g_x1[ROWS * DM_];
__device__ float  g_gate[ROWS * DI_];     // raw fp32 gate (gelu input)
__device__ __half g_act[ROWS * DI_];      // gelu(gate)*up (fp16)
__device__ float2 g_rope[S_ * 32];
// fp16 transposed weights [N][K]
__device__ __half g_wqkv[DQKV * DM_];
__device__ __half g_wo  [DM_ * DM_];
__device__ __half g_wi0 [DI_ * DM_];
__device__ __half g_wi1 [DI_ * DM_];
__device__ __half g_wmo [DM_ * DI_];

// ---------------- TF32 rounding (attention internals) ----------------
__device__ __forceinline__ float tf32r(float x) {
    uint32_t u;
    asm("cvt.rna.tf32.f32 %0, %1;" : "=r"(u) : "f"(x));
    return __uint_as_float(u);
}

__device__ __forceinline__ float warpSum(float v) {
    #pragma unroll
    for (int o = 16; o; o >>= 1) v += __shfl_xor_sync(0xffffffffu, v, o);
    return v;
}

// ---------------- weight transpose + fp16 convert: out[N][K] = h(in[K][N]^T) -
__global__ void wtransh_kernel(const float* __restrict__ in, __half* __restrict__ out,
                               int K, int N) {
    __shared__ float t[32][33];
    int k0 = blockIdx.x * 32, n0 = blockIdx.y * 32;
    int tx = threadIdx.x, ty = threadIdx.y;
    #pragma unroll
    for (int i = ty; i < 32; i += 8)
        t[i][tx] = in[(size_t)(k0 + i) * N + n0 + tx];
    __syncthreads();
    #pragma unroll
    for (int i = ty; i < 32; i += 8)
        out[(size_t)(n0 + i) * K + k0 + tx] = __float2half_rn(t[tx][i]);
}

// ---------------- RoPE table ----------------
__global__ void ropetab_kernel(float2* __restrict__ tab) {
    int idx = blockIdx.x * blockDim.x + threadIdx.x;
    if (idx >= S_ * 32) return;
    int s = idx >> 5, d = idx & 31;
    float w = (float)(2 * d) / (float)DH_;
    float inv_freq = 1.0f / powf(10000.0f, w);
    float ang = (float)s * inv_freq;
    tab[idx] = make_float2(cosf(ang), sinf(ang));
}

// ---------------- RMSNorm (fp16 output) ----------------
__global__ void rmsnorm_kernel(const float* __restrict__ x,
                               const float* __restrict__ gamma,
                               __half* __restrict__ o) {
    int row = blockIdx.x;
    const float* xr = x + (size_t)row * DM_;
    float s = 0.f;
    for (int i = threadIdx.x; i < DM_; i += 256) { float v = xr[i]; s += v * v; }
    __shared__ float red[8];
    float w = warpSum(s);
    if ((threadIdx.x & 31) == 0) red[threadIdx.x >> 5] = w;
    __syncthreads();
    float tot = 0.f;
    #pragma unroll
    for (int i = 0; i < 8; i++) tot += red[i];
    float inv = rsqrtf(tot / (float)DM_ + 1e-5f);
    __half* orow = o + (size_t)row * DM_;
    for (int i = threadIdx.x; i < DM_; i += 256)
        orow[i] = __float2half_rn(xr[i] * inv * gamma[i]);
}

// =================== fp16 tensor-core GEMM: 128x128x32, 4-stage cp.async ====
// A[M][K] fp16, Bt[N][K] fp16. mode 0: C=acc(f32) ; 1: C=Res+acc(f32) ;
// 2: C(half) = h(gelu(Res) * acc)
#define BM 128
#define BN 128
#define BK 32
#define HSTRIDE 40                                    // halves per smem row
#define STAGE_HALVES ((BM + BN) * HSTRIDE)            // 10240
#define NSTAGE 4
#define GEMM_SMEM_BYTES (NSTAGE * STAGE_HALVES * 2)   // 81920

__device__ __forceinline__ void mma_f16(float c[4], const uint32_t a[4], const uint32_t b[2]) {
    asm volatile(
        "mma.sync.aligned.m16n8k16.row.col.f32.f16.f16.f32 "
        "{%0,%1,%2,%3}, {%4,%5,%6,%7}, {%8,%9}, {%0,%1,%2,%3};"
        : "+f"(c[0]), "+f"(c[1]), "+f"(c[2]), "+f"(c[3])
        : "r"(a[0]), "r"(a[1]), "r"(a[2]), "r"(a[3]), "r"(b[0]), "r"(b[1]));
}

__device__ __forceinline__ void cp16(const __half* dst_smem, const __half* src) {
    uint32_t d = (uint32_t)__cvta_generic_to_shared(dst_smem);
    asm volatile("cp.async.cg.shared.global [%0], [%1], 16;" :: "r"(d), "l"(src));
}

__device__ __forceinline__ float gelu_t(float x) {
    float t = tanhf(0.7978845608028654f * (x + 0.044715f * x * x * x));
    return 0.5f * x * (1.0f + t);
}

__global__ __launch_bounds__(256, 2)
void mma_gemm_kernel(const __half* __restrict__ A, const __half* __restrict__ Bt,
                     const float* __restrict__ Res, void* __restrict__ Cv,
                     int M, int N, int K, int mode) {
    extern __shared__ __half smh[];

    const int tid  = threadIdx.x;
    const int lane = tid & 31;
    const int warp = tid >> 5;
    const int gid  = lane >> 2;
    const int tg   = lane & 3;
    const int wm   = warp >> 1;
    const int wn   = warp & 1;

    const int bm = blockIdx.y * BM;
    const int bn = blockIdx.x * BN;

    float acc[2][8][4];
    #pragma unroll
    for (int i = 0; i < 2; i++)
        #pragma unroll
        for (int j = 0; j < 8; j++)
            #pragma unroll
            for (int l = 0; l < 4; l++) acc[i][j][l] = 0.f;

    const int ntiles = K / BK;

    // A tile: 128 rows x 32 halves (4x16B chunks/row); B tile same.
    #define ISSUE_TILE(t, buf) do {                                            \
        __half* As_ = smh + (buf) * STAGE_HALVES;                               \
        __half* Bs_ = As_ + BM * HSTRIDE;                                       \
        int k0_ = (t) * BK;                                                     \
        _Pragma("unroll")                                                       \
        for (int u = 0; u < 2; u++) {                                           \
            int i = tid + u * 256;                                              \
            int r = i >> 2, c = i & 3;                                          \
            cp16(&As_[r * HSTRIDE + c * 8],                                     \
                 &A[(size_t)(bm + r) * K + k0_ + c * 8]);                       \
        }                                                                       \
        _Pragma("unroll")                                                       \
        for (int u = 0; u < 2; u++) {                                           \
            int i = tid + u * 256;                                              \
            int r = i >> 2, c = i & 3;                                          \
            cp16(&Bs_[r * HSTRIDE + c * 8],                                     \
                 &Bt[(size_t)(bn + r) * K + k0_ + c * 8]);                      \
        }                                                                       \
        asm volatile("cp.async.commit_group;");                                 \
    } while (0)

    ISSUE_TILE(0, 0);
    if (ntiles > 1) ISSUE_TILE(1, 1);
    if (ntiles > 2) ISSUE_TILE(2, 2);

    int buf = 0;
    for (int t = 0; t < ntiles; t++) {
        int rem = ntiles - 1 - t;   // groups issued beyond tile t at loop top
        if (rem >= 2)      asm volatile("cp.async.wait_group 2;");
        else if (rem == 1) asm volatile("cp.async.wait_group 1;");
        else               asm volatile("cp.async.wait_group 0;");
        __syncthreads();

        if (t + 3 < ntiles) {
            int nb = buf + 3; if (nb >= NSTAGE) nb -= NSTAGE;
            ISSUE_TILE(t + 3, nb);
        }

        const __half* As = smh + buf * STAGE_HALVES;
        const __half* Bs = As + BM * HSTRIDE;

        #pragma unroll
        for (int ks = 0; ks < 2; ks++) {
            uint32_t af[2][4], bf[8][2];
            const int kb = ks * 16 + 2 * tg;   // half offset (4B aligned)
            #pragma unroll
            for (int mt = 0; mt < 2; mt++) {
                int r = wm * 32 + mt * 16 + gid;
                af[mt][0] = *(const uint32_t*)&As[r * HSTRIDE + kb];
                af[mt][1] = *(const uint32_t*)&As[(r + 8) * HSTRIDE + kb];
                af[mt][2] = *(const uint32_t*)&As[r * HSTRIDE + kb + 8];
                af[mt][3] = *(const uint32_t*)&As[(r + 8) * HSTRIDE + kb + 8];
            }
            #pragma unroll
            for (int nt = 0; nt < 8; nt++) {
                int n = wn * 64 + nt * 8 + gid;
                bf[nt][0] = *(const uint32_t*)&Bs[n * HSTRIDE + kb];
                bf[nt][1] = *(const uint32_t*)&Bs[n * HSTRIDE + kb + 8];
            }
            #pragma unroll
            for (int mt = 0; mt < 2; mt++)
                #pragma unroll
                for (int nt = 0; nt < 8; nt++)
                    mma_f16(acc[mt][nt], af[mt], bf[nt]);
        }

        buf++; if (buf >= NSTAGE) buf = 0;
    }

    #pragma unroll
    for (int mt = 0; mt < 2; mt++) {
        #pragma unroll
        for (int nt = 0; nt < 8; nt++) {
            int m0 = bm + wm * 32 + mt * 16 + gid;
            int n0 = bn + wn * 64 + nt * 8 + tg * 2;
            float2 v0 = make_float2(acc[mt][nt][0], acc[mt][nt][1]);
            float2 v1 = make_float2(acc[mt][nt][2], acc[mt][nt][3]);
            if (mode == 2) {
                float2 r0 = *(const float2*)&Res[(size_t)m0 * N + n0];
                float2 r1 = *(const float2*)&Res[(size_t)(m0 + 8) * N + n0];
                __half* Ch = (__half*)Cv;
                *(__half2*)&Ch[(size_t)m0 * N + n0] =
                    __floats2half2_rn(gelu_t(r0.x) * v0.x, gelu_t(r0.y) * v0.y);
                *(__half2*)&Ch[(size_t)(m0 + 8) * N + n0] =
                    __floats2half2_rn(gelu_t(r1.x) * v1.x, gelu_t(r1.y) * v1.y);
            } else {
                if (mode == 1) {
                    float2 r0 = *(const float2*)&Res[(size_t)m0 * N + n0];
                    float2 r1 = *(const float2*)&Res[(size_t)(m0 + 8) * N + n0];
                    v0.x += r0.x; v0.y += r0.y;
                    v1.x += r1.x; v1.y += r1.y;
                }
                float* C = (float*)Cv;
                *(float2*)&C[(size_t)m0 * N + n0] = v0;
                *(float2*)&C[(size_t)(m0 + 8) * N + n0] = v1;
            }
        }
    }
}

// =================== tiled sliding-window attention (fp16 output) ====
#define QT 64
#define KT 192
#define SSTR 196
#define ATTN_Q_FLOATS   (QT * DH_)
#define ATTN_K_FLOATS   (KT * DH_)
#define ATTN_S_FLOATS   (QT * SSTR)
#define ATTN_SMEM_FLOATS (ATTN_Q_FLOATS + 2 * ATTN_K_FLOATS + ATTN_S_FLOATS)
#define ATTN_SMEM_BYTES  (ATTN_SMEM_FLOATS * 4)

__device__ __forceinline__ int ksw(int row, int chunk) {
    return row * DH_ + 4 * (chunk ^ ((row >> 2) & 15));
}

__device__ __forceinline__ void rope4t(const float2* __restrict__ tab, int s, int c,
                                       float4& lo, float4& hi) {
    #pragma unroll
    for (int l = 0; l < 4; l++) {
        float2 cs = tab[s * 32 + c * 4 + l];
        float x1 = (&lo.x)[l];
        float x2 = (&hi.x)[l];
        (&lo.x)[l] = tf32r(x1 * cs.x - x2 * cs.y);
        (&hi.x)[l] = tf32r(x2 * cs.x + x1 * cs.y);
    }
}

__global__ __launch_bounds__(512, 1)
void attn_tile_kernel(const float* __restrict__ qkv, const int* __restrict__ pmask,
                      const float2* __restrict__ ropeT, __half* __restrict__ out) {
    extern __shared__ float sm[];
    float* Qs = sm;
    float* Ks = Qs + ATTN_Q_FLOATS;
    float* Vs = Ks + ATTN_K_FLOATS;
    float* Sc = Vs + ATTN_K_FLOATS;

    const int qt0 = blockIdx.x * QT;
    const int h   = blockIdx.y;
    const int b   = blockIdx.z;
    const int tid = threadIdx.x;

    {
        int r = tid >> 3, c = tid & 7;
        int s = qt0 + r;
        size_t base = (size_t)(b * S_ + s) * DQKV + h * DH_;
        float4 lo = *(const float4*)&qkv[base + c * 4];
        float4 hi = *(const float4*)&qkv[base + 32 + c * 4];
        rope4t(ropeT, s, c, lo, hi);
        *(float4*)&Qs[r * DH_ + c * 4] = lo;
        *(float4*)&Qs[r * DH_ + 32 + c * 4] = hi;
    }
    for (int i = tid; i < KT * 8; i += 512) {
        int r = i >> 3, c = i & 7;
        int j = qt0 - WIN + r;
        float4 klo = make_float4(0.f,0.f,0.f,0.f), khi = klo, vlo = klo, vhi = klo;
        if (j >= 0 && j < S_) {
            size_t base = (size_t)(b * S_ + j) * DQKV + h * DH_;
            klo = *(const float4*)&qkv[base + DM_ + c * 4];
            khi = *(const float4*)&qkv[base + DM_ + 32 + c * 4];
            rope4t(ropeT, j, c, klo, khi);
            vlo = *(const float4*)&qkv[base + 2 * DM_ + c * 4];
            vhi = *(const float4*)&qkv[base + 2 * DM_ + 32 + c * 4];
            vlo.x = tf32r(vlo.x); vlo.y = tf32r(vlo.y); vlo.z = tf32r(vlo.z); vlo.w = tf32r(vlo.w);
            vhi.x = tf32r(vhi.x); vhi.y = tf32r(vhi.y); vhi.z = tf32r(vhi.z); vhi.w = tf32r(vhi.w);
        }
        *(float4*)&Ks[ksw(r, c)] = klo;
        *(float4*)&Ks[ksw(r, c + 8)] = khi;
        *(float4*)&Vs[r * DH_ + c * 4] = vlo;
        *(float4*)&Vs[r * DH_ + 32 + c * 4] = vhi;
    }
    __syncthreads();

    {
        const int tk = tid & 15;
        const int tq = tid >> 4;
        #pragma unroll
        for (int kp = 0; kp < 3; kp++) {
            const int kbase = kp * 64 + tk * 4;
            float acc[2][4];
            #pragma unroll
            for (int i = 0; i < 2; i++)
                #pragma unroll
                for (int u = 0; u < 4; u++) acc[i][u] = 0.f;

            for (int c = 0; c < 16; c++) {
                float4 qv[2], kv[4];
                #pragma unroll
                for (int i = 0; i < 2; i++)
                    qv[i] = *(const float4*)&Qs[(tq * 2 + i) * DH_ + c * 4];
                #pragma unroll
                for (int u = 0; u < 4; u++)
                    kv[u] = *(const float4*)&Ks[ksw(kbase + u, c)];
                #pragma unroll
                for (int i = 0; i < 2; i++)
                    #pragma unroll
                    for (int u = 0; u < 4; u++)
                        acc[i][u] += qv[i].x * kv[u].x + qv[i].y * kv[u].y
                                   + qv[i].z * kv[u].z + qv[i].w * kv[u].w;
            }
            #pragma unroll
            for (int i = 0; i < 2; i++) {
                int ql = tq * 2 + i;
                int qg = qt0 + ql;
                #pragma unroll
                for (int u = 0; u < 4; u++) {
                    int kr = kbase + u;
                    int j = qt0 - WIN + kr;
                    float s;
                    if (j < 0 || j >= S_) {
                        s = -1e30f;
                    } else {
                        s = acc[i][u] * 0.125f;
                        int diff = j - qg;
                        if (diff > WIN || diff < -WIN) s -= 10000.0f;
                        if (pmask[b * S_ + j] == 0)    s -= 10000.0f;
                    }
                    Sc[ql * SSTR + kr] = s;
                }
            }
        }
    }
    __syncthreads();

    {
        const int row = tid >> 3, sub = tid & 7;
        float m = -1e30f;
        for (int k = sub; k < KT; k += 8) m = fmaxf(m, Sc[row * SSTR + k]);
        m = fmaxf(m, __shfl_xor_sync(0xffffffffu, m, 1));
        m = fmaxf(m, __shfl_xor_sync(0xffffffffu, m, 2));
        m = fmaxf(m, __shfl_xor_sync(0xffffffffu, m, 4));
        float ssum = 0.f;
        for (int k = sub; k < KT; k += 8) {
            float e = expf(Sc[row * SSTR + k] - m);
            Sc[row * SSTR + k] = e;
            ssum += e;
        }
        ssum += __shfl_xor_sync(0xffffffffu, ssum, 1);
        ssum += __shfl_xor_sync(0xffffffffu, ssum, 2);
        ssum += __shfl_xor_sync(0xffffffffu, ssum, 4);
        for (int k = sub; k < KT; k += 8)
            Sc[row * SSTR + k] = tf32r(Sc[row * SSTR + k] / ssum);
    }
    __syncthreads();

    {
        const int d4 = (tid & 15) * 4;
        const int q2 = (tid >> 4) * 2;
        float o[2][4];
        #pragma unroll
        for (int i = 0; i < 2; i++)
            #pragma unroll
            for (int u = 0; u < 4; u++) o[i][u] = 0.f;

        for (int k = 0; k < KT; k += 4) {
            float4 pv[2];
            #pragma unroll
            for (int i = 0; i < 2; i++)
                pv[i] = *(const float4*)&Sc[(q2 + i) * SSTR + k];
            #pragma unroll
            for (int kk = 0; kk < 4; kk++) {
                float4 vv = *(const float4*)&Vs[(k + kk) * DH_ + d4];
                #pragma unroll
                for (int i = 0; i < 2; i++) {
                    float p = (kk == 0) ? pv[i].x : (kk == 1) ? pv[i].y : (kk == 2) ? pv[i].z : pv[i].w;
                    o[i][0] += p * vv.x;
                    o[i][1] += p * vv.y;
                    o[i][2] += p * vv.z;
                    o[i][3] += p * vv.w;
                }
            }
        }
        #pragma unroll
        for (int i = 0; i < 2; i++) {
            size_t idx = (size_t)(b * S_ + qt0 + q2 + i) * DM_ + h * DH_ + d4;
            *(__half2*)&out[idx]     = __floats2half2_rn(o[i][0], o[i][1]);
            *(__half2*)&out[idx + 2] = __floats2half2_rn(o[i][2], o[i][3]);
        }
    }
}

// ---------------- launch ----------------
extern "C" void kernel_launch(void* const* d_in, const int* in_sizes, int n_in,
                              void* d_out, int out_size) {
    const float* x          = (const float*)d_in[0];
    const int*   pmask      = (const int*)  d_in[1];
    const float* w_qkv      = (const float*)d_in[2];
    const float* w_o        = (const float*)d_in[3];
    const float* gamma_attn = (const float*)d_in[4];
    const float* gamma_mlp  = (const float*)d_in[5];
    const float* w_i0       = (const float*)d_in[6];
    const float* w_i1       = (const float*)d_in[7];
    const float* w_mo       = (const float*)d_in[8];
    float* out = (float*)d_out;

    __half *h, *attn, *act, *wqkv, *wo, *wi0, *wi1, *wmo;
    float *qkv, *x1, *gate;
    float2* ropeT;
    cudaGetSymbolAddress((void**)&h,    g_h);
    cudaGetSymbolAddress((void**)&qkv,  g_qkv);
    cudaGetSymbolAddress((void**)&attn, g_attn);
    cudaGetSymbolAddress((void**)&x1,   g_x1);
    cudaGetSymbolAddress((void**)&gate, g_gate);
    cudaGetSymbolAddress((void**)&act,  g_act);
    cudaGetSymbolAddress((void**)&ropeT, g_rope);
    cudaGetSymbolAddress((void**)&wqkv, g_wqkv);
    cudaGetSymbolAddress((void**)&wo,   g_wo);
    cudaGetSymbolAddress((void**)&wi0,  g_wi0);
    cudaGetSymbolAddress((void**)&wi1,  g_wi1);
    cudaGetSymbolAddress((void**)&wmo,  g_wmo);

    cudaFuncSetAttribute(mma_gemm_kernel,
                         cudaFuncAttributeMaxDynamicSharedMemorySize, GEMM_SMEM_BYTES);
    cudaFuncSetAttribute(attn_tile_kernel,
                         cudaFuncAttributeMaxDynamicSharedMemorySize, ATTN_SMEM_BYTES);

    // weight transpose + fp16 convert (once per launch, deterministic)
    dim3 tb(32, 8);
    wtransh_kernel<<<dim3(DM_ / 32, DQKV / 32), tb>>>(w_qkv, wqkv, DM_, DQKV);
    wtransh_kernel<<<dim3(DM_ / 32, DM_  / 32), tb>>>(w_o,   wo,   DM_, DM_);
    wtransh_kernel<<<dim3(DM_ / 32, DI_  / 32), tb>>>(w_i0,  wi0,  DM_, DI_);
    wtransh_kernel<<<dim3(DM_ / 32, DI_  / 32), tb>>>(w_i1,  wi1,  DM_, DI_);
    wtransh_kernel<<<dim3(DI_ / 32, DM_  / 32), tb>>>(w_mo,  wmo,  DI_, DM_);
    ropetab_kernel<<<(S_ * 32 + 255) / 256, 256>>>(ropeT);

    rmsnorm_kernel<<<ROWS, 256>>>(x, gamma_attn, h);
    mma_gemm_kernel<<<dim3(DQKV / BN, ROWS / BM), 256, GEMM_SMEM_BYTES>>>(
        h, wqkv, nullptr, qkv, ROWS, DQKV, DM_, 0);
    attn_tile_kernel<<<dim3(S_ / QT, H_, B_), 512, ATTN_SMEM_BYTES>>>(qkv, pmask, ropeT, attn);
    mma_gemm_kernel<<<dim3(DM_ / BN, ROWS / BM), 256, GEMM_SMEM_BYTES>>>(
        attn, wo, x, x1, ROWS, DM_, DM_, 1);
    rmsnorm_kernel<<<ROWS, 256>>>(x1, gamma_mlp, h);
    mma_gemm_kernel<<<dim3(DI_ / BN, ROWS / BM), 256, GEMM_SMEM_BYTES>>>(
        h, wi0, nullptr, gate, ROWS, DI_, DM_, 0);
    mma_gemm_kernel<<<dim3(DI_ / BN, ROWS / BM), 256, GEMM_SMEM_BYTES>>>(
        h, wi1, gate, act, ROWS, DI_, DM_, 2);
    mma_gemm_kernel<<<dim3(DM_ / BN, ROWS / BM), 256, GEMM_SMEM_BYTES>>>(
        act, wmo, x1, out, ROWS, DM_, DI_, 1);
}

// round 11
// speedup vs baseline: 2.1416x; 1.3887x over previous
#include <cuda_runtime.h>
#include <cuda_fp16.h>
#include <math.h>
#include <stdint.h>

// ---------------- problem constants ----------------
#define B_   2
#define S_   4096
#define DM_  768
#define DI_  1152
#define H_   12
#define DH_  64
#define ROWS (B_ * S_)          // 8192
#define DQKV (3 * DM_)          // 2304
#define WIN  64                 // WINDOW/2

// ---------------- scratch ----------------
__device__ __half g_h[ROWS * DM_];        // rmsnorm out (fp16)
__device__ float  g_qkv[ROWS * DQKV];     // qkv (fp32)
__device__ __half g_attn[ROWS * DM_];     // attention out (fp16)
__device__ float  g_x1[ROWS * DM_];
__device__ float  g_gate[ROWS * DI_];
__device__ __half g_act[ROWS * DI_];
__device__ float2 g_rope[S_ * 32];
// fp16 transposed weights [N][K]
__device__ __half g_wqkv[DQKV * DM_];
__device__ __half g_wo  [DM_ * DM_];
__device__ __half g_wi0 [DI_ * DM_];
__device__ __half g_wi1 [DI_ * DM_];
__device__ __half g_wmo [DM_ * DI_];

__device__ __forceinline__ float warpSum(float v) {
    #pragma unroll
    for (int o = 16; o; o >>= 1) v += __shfl_xor_sync(0xffffffffu, v, o);
    return v;
}

// ---------------- weight transpose + fp16 convert ----------------
__global__ void wtransh_kernel(const float* __restrict__ in, __half* __restrict__ out,
                               int K, int N) {
    __shared__ float t[32][33];
    int k0 = blockIdx.x * 32, n0 = blockIdx.y * 32;
    int tx = threadIdx.x, ty = threadIdx.y;
    #pragma unroll
    for (int i = ty; i < 32; i += 8)
        t[i][tx] = in[(size_t)(k0 + i) * N + n0 + tx];
    __syncthreads();
    #pragma unroll
    for (int i = ty; i < 32; i += 8)
        out[(size_t)(n0 + i) * K + k0 + tx] = __float2half_rn(t[tx][i]);
}

// ---------------- RoPE table ----------------
__global__ void ropetab_kernel(float2* __restrict__ tab) {
    int idx = blockIdx.x * blockDim.x + threadIdx.x;
    if (idx >= S_ * 32) return;
    int s = idx >> 5, d = idx & 31;
    float w = (float)(2 * d) / (float)DH_;
    float inv_freq = 1.0f / powf(10000.0f, w);
    float ang = (float)s * inv_freq;
    tab[idx] = make_float2(cosf(ang), sinf(ang));
}

// ---------------- RMSNorm (fp16 output) ----------------
__global__ void rmsnorm_kernel(const float* __restrict__ x,
                               const float* __restrict__ gamma,
                               __half* __restrict__ o) {
    int row = blockIdx.x;
    const float* xr = x + (size_t)row * DM_;
    float s = 0.f;
    for (int i = threadIdx.x; i < DM_; i += 256) { float v = xr[i]; s += v * v; }
    __shared__ float red[8];
    float w = warpSum(s);
    if ((threadIdx.x & 31) == 0) red[threadIdx.x >> 5] = w;
    __syncthreads();
    float tot = 0.f;
    #pragma unroll
    for (int i = 0; i < 8; i++) tot += red[i];
    float inv = rsqrtf(tot / (float)DM_ + 1e-5f);
    __half* orow = o + (size_t)row * DM_;
    for (int i = threadIdx.x; i < DM_; i += 256)
        orow[i] = __float2half_rn(xr[i] * inv * gamma[i]);
}

// =================== fp16 tensor-core GEMM (R10, unchanged) ====
#define BM 128
#define BN 128
#define BK 32
#define HSTRIDE 40
#define STAGE_HALVES ((BM + BN) * HSTRIDE)
#define NSTAGE 4
#define GEMM_SMEM_BYTES (NSTAGE * STAGE_HALVES * 2)

__device__ __forceinline__ void mma_f16(float c[4], const uint32_t a[4], const uint32_t b[2]) {
    asm volatile(
        "mma.sync.aligned.m16n8k16.row.col.f32.f16.f16.f32 "
        "{%0,%1,%2,%3}, {%4,%5,%6,%7}, {%8,%9}, {%0,%1,%2,%3};"
        : "+f"(c[0]), "+f"(c[1]), "+f"(c[2]), "+f"(c[3])
        : "r"(a[0]), "r"(a[1]), "r"(a[2]), "r"(a[3]), "r"(b[0]), "r"(b[1]));
}

__device__ __forceinline__ void cp16(const __half* dst_smem, const __half* src) {
    uint32_t d = (uint32_t)__cvta_generic_to_shared(dst_smem);
    asm volatile("cp.async.cg.shared.global [%0], [%1], 16;" :: "r"(d), "l"(src));
}

__device__ __forceinline__ float gelu_t(float x) {
    float t = tanhf(0.7978845608028654f * (x + 0.044715f * x * x * x));
    return 0.5f * x * (1.0f + t);
}

__global__ __launch_bounds__(256, 2)
void mma_gemm_kernel(const __half* __restrict__ A, const __half* __restrict__ Bt,
                     const float* __restrict__ Res, void* __restrict__ Cv,
                     int M, int N, int K, int mode) {
    extern __shared__ __half smh[];

    const int tid  = threadIdx.x;
    const int lane = tid & 31;
    const int warp = tid >> 5;
    const int gid  = lane >> 2;
    const int tg   = lane & 3;
    const int wm   = warp >> 1;
    const int wn   = warp & 1;

    const int bm = blockIdx.y * BM;
    const int bn = blockIdx.x * BN;

    float acc[2][8][4];
    #pragma unroll
    for (int i = 0; i < 2; i++)
        #pragma unroll
        for (int j = 0; j < 8; j++)
            #pragma unroll
            for (int l = 0; l < 4; l++) acc[i][j][l] = 0.f;

    const int ntiles = K / BK;

    #define ISSUE_TILE(t, buf) do {                                            \
        __half* As_ = smh + (buf) * STAGE_HALVES;                               \
        __half* Bs_ = As_ + BM * HSTRIDE;                                       \
        int k0_ = (t) * BK;                                                     \
        _Pragma("unroll")                                                       \
        for (int u = 0; u < 2; u++) {                                           \
            int i = tid + u * 256;                                              \
            int r = i >> 2, c = i & 3;                                          \
            cp16(&As_[r * HSTRIDE + c * 8],                                     \
                 &A[(size_t)(bm + r) * K + k0_ + c * 8]);                       \
        }                                                                       \
        _Pragma("unroll")                                                       \
        for (int u = 0; u < 2; u++) {                                           \
            int i = tid + u * 256;                                              \
            int r = i >> 2, c = i & 3;                                          \
            cp16(&Bs_[r * HSTRIDE + c * 8],                                     \
                 &Bt[(size_t)(bn + r) * K + k0_ + c * 8]);                      \
        }                                                                       \
        asm volatile("cp.async.commit_group;");                                 \
    } while (0)

    ISSUE_TILE(0, 0);
    if (ntiles > 1) ISSUE_TILE(1, 1);
    if (ntiles > 2) ISSUE_TILE(2, 2);

    int buf = 0;
    for (int t = 0; t < ntiles; t++) {
        int rem = ntiles - 1 - t;
        if (rem >= 2)      asm volatile("cp.async.wait_group 2;");
        else if (rem == 1) asm volatile("cp.async.wait_group 1;");
        else               asm volatile("cp.async.wait_group 0;");
        __syncthreads();

        if (t + 3 < ntiles) {
            int nb = buf + 3; if (nb >= NSTAGE) nb -= NSTAGE;
            ISSUE_TILE(t + 3, nb);
        }

        const __half* As = smh + buf * STAGE_HALVES;
        const __half* Bs = As + BM * HSTRIDE;

        #pragma unroll
        for (int ks = 0; ks < 2; ks++) {
            uint32_t af[2][4], bf[8][2];
            const int kb = ks * 16 + 2 * tg;
            #pragma unroll
            for (int mt = 0; mt < 2; mt++) {
                int r = wm * 32 + mt * 16 + gid;
                af[mt][0] = *(const uint32_t*)&As[r * HSTRIDE + kb];
                af[mt][1] = *(const uint32_t*)&As[(r + 8) * HSTRIDE + kb];
                af[mt][2] = *(const uint32_t*)&As[r * HSTRIDE + kb + 8];
                af[mt][3] = *(const uint32_t*)&As[(r + 8) * HSTRIDE + kb + 8];
            }
            #pragma unroll
            for (int nt = 0; nt < 8; nt++) {
                int n = wn * 64 + nt * 8 + gid;
                bf[nt][0] = *(const uint32_t*)&Bs[n * HSTRIDE + kb];
                bf[nt][1] = *(const uint32_t*)&Bs[n * HSTRIDE + kb + 8];
            }
            #pragma unroll
            for (int mt = 0; mt < 2; mt++)
                #pragma unroll
                for (int nt = 0; nt < 8; nt++)
                    mma_f16(acc[mt][nt], af[mt], bf[nt]);
        }

        buf++; if (buf >= NSTAGE) buf = 0;
    }

    #pragma unroll
    for (int mt = 0; mt < 2; mt++) {
        #pragma unroll
        for (int nt = 0; nt < 8; nt++) {
            int m0 = bm + wm * 32 + mt * 16 + gid;
            int n0 = bn + wn * 64 + nt * 8 + tg * 2;
            float2 v0 = make_float2(acc[mt][nt][0], acc[mt][nt][1]);
            float2 v1 = make_float2(acc[mt][nt][2], acc[mt][nt][3]);
            if (mode == 2) {
                float2 r0 = *(const float2*)&Res[(size_t)m0 * N + n0];
                float2 r1 = *(const float2*)&Res[(size_t)(m0 + 8) * N + n0];
                __half* Ch = (__half*)Cv;
                *(__half2*)&Ch[(size_t)m0 * N + n0] =
                    __floats2half2_rn(gelu_t(r0.x) * v0.x, gelu_t(r0.y) * v0.y);
                *(__half2*)&Ch[(size_t)(m0 + 8) * N + n0] =
                    __floats2half2_rn(gelu_t(r1.x) * v1.x, gelu_t(r1.y) * v1.y);
            } else {
                if (mode == 1) {
                    float2 r0 = *(const float2*)&Res[(size_t)m0 * N + n0];
                    float2 r1 = *(const float2*)&Res[(size_t)(m0 + 8) * N + n0];
                    v0.x += r0.x; v0.y += r0.y;
                    v1.x += r1.x; v1.y += r1.y;
                }
                float* C = (float*)Cv;
                *(float2*)&C[(size_t)m0 * N + n0] = v0;
                *(float2*)&C[(size_t)(m0 + 8) * N + n0] = v1;
            }
        }
    }
}

// =================== tensor-core sliding-window attention ====
#define QT 64
#define KT 192
#define KTP 72     // halves stride for Qh/Kh rows
#define VTP 200    // halves stride for Vt rows (d-major, k-contiguous)
#define ATTN_SMEM_BYTES ((QT * KTP + KT * KTP + DH_ * VTP) * 2 + KT * 4)

// rope one chunk-pair in fp32, emit fp16 (single rounding, matches reference order)
__device__ __forceinline__ void rope_h(const float2* __restrict__ tab, int s, int c,
                                       float4 lo, float4 hi, __half2 olo[2], __half2 ohi[2]) {
    float rlo[4], rhi[4];
    #pragma unroll
    for (int l = 0; l < 4; l++) {
        float2 cs = tab[s * 32 + c * 4 + l];
        float x1 = (&lo.x)[l];
        float x2 = (&hi.x)[l];
        rlo[l] = x1 * cs.x - x2 * cs.y;
        rhi[l] = x2 * cs.x + x1 * cs.y;
    }
    olo[0] = __floats2half2_rn(rlo[0], rlo[1]);
    olo[1] = __floats2half2_rn(rlo[2], rlo[3]);
    ohi[0] = __floats2half2_rn(rhi[0], rhi[1]);
    ohi[1] = __floats2half2_rn(rhi[2], rhi[3]);
}

__global__ __launch_bounds__(128)
void attn_mma_kernel(const float* __restrict__ qkv, const int* __restrict__ pmask,
                     const float2* __restrict__ ropeT, __half* __restrict__ out) {
    extern __shared__ __half smh[];
    __half* Qh = smh;                      // [QT][KTP]
    __half* Kh = Qh + QT * KTP;            // [KT][KTP]
    __half* Vt = Kh + KT * KTP;            // [DH][VTP]  (transposed V)
    float*  pm = (float*)(Vt + DH_ * VTP); // [KT]

    const int qt0 = blockIdx.x * QT;
    const int h   = blockIdx.y;
    const int b   = blockIdx.z;
    const int tid = threadIdx.x;
    const int lane = tid & 31;
    const int warp = tid >> 5;     // 0..3
    const int gid  = lane >> 2;
    const int tg   = lane & 3;

    // ---- per-key additive mask (oob -> -1e30 => exp == 0 exactly) ----
    for (int i = tid; i < KT; i += 128) {
        int j = qt0 - WIN + i;
        pm[i] = (j < 0 || j >= S_) ? -1e30f : (pmask[b * S_ + j] ? 0.f : -10000.0f);
    }
    // ---- Q: 64 rows x 8 chunk-pairs ----
    #pragma unroll
    for (int it = 0; it < 4; it++) {
        int i = tid + it * 128;
        int r = i >> 3, c = i & 7;
        int s = qt0 + r;
        size_t base = (size_t)(b * S_ + s) * DQKV + h * DH_;
        float4 lo = *(const float4*)&qkv[base + c * 4];
        float4 hi = *(const float4*)&qkv[base + 32 + c * 4];
        __half2 olo[2], ohi[2];
        rope_h(ropeT, s, c, lo, hi, olo, ohi);
        *(__half2*)&Qh[r * KTP + c * 4]      = olo[0];
        *(__half2*)&Qh[r * KTP + c * 4 + 2]  = olo[1];
        *(__half2*)&Qh[r * KTP + 32 + c * 4]     = ohi[0];
        *(__half2*)&Qh[r * KTP + 32 + c * 4 + 2] = ohi[1];
    }
    // ---- K: 192 rows x 8 chunk-pairs (oob -> 0) ----
    #pragma unroll
    for (int it = 0; it < 12; it++) {
        int i = tid + it * 128;
        int r = i >> 3, c = i & 7;
        int j = qt0 - WIN + r;
        __half2 olo[2], ohi[2];
        if (j >= 0 && j < S_) {
            size_t base = (size_t)(b * S_ + j) * DQKV + DM_ + h * DH_;
            float4 lo = *(const float4*)&qkv[base + c * 4];
            float4 hi = *(const float4*)&qkv[base + 32 + c * 4];
            rope_h(ropeT, j, c, lo, hi, olo, ohi);
        } else {
            olo[0] = olo[1] = ohi[0] = ohi[1] = __floats2half2_rn(0.f, 0.f);
        }
        *(__half2*)&Kh[r * KTP + c * 4]      = olo[0];
        *(__half2*)&Kh[r * KTP + c * 4 + 2]  = olo[1];
        *(__half2*)&Kh[r * KTP + 32 + c * 4]     = ohi[0];
        *(__half2*)&Kh[r * KTP + 32 + c * 4 + 2] = ohi[1];
    }
    // ---- V transposed: Vt[d][k] ----
    #pragma unroll
    for (int it = 0; it < 24; it++) {
        int i = tid + it * 128;
        int r = i >> 4, c = i & 15;       // key row r, d-chunk c
        int j = qt0 - WIN + r;
        float4 v = make_float4(0.f, 0.f, 0.f, 0.f);
        if (j >= 0 && j < S_)
            v = *(const float4*)&qkv[(size_t)(b * S_ + j) * DQKV + 2 * DM_ + h * DH_ + c * 4];
        Vt[(c * 4 + 0) * VTP + r] = __float2half_rn(v.x);
        Vt[(c * 4 + 1) * VTP + r] = __float2half_rn(v.y);
        Vt[(c * 4 + 2) * VTP + r] = __float2half_rn(v.z);
        Vt[(c * 4 + 3) * VTP + r] = __float2half_rn(v.w);
    }
    __syncthreads();

    // ---- QK^T: warp owns rows rq..rq+15 ----
    const int rq = warp * 16;
    float acc[24][4];
    #pragma unroll
    for (int nt = 0; nt < 24; nt++)
        #pragma unroll
        for (int e = 0; e < 4; e++) acc[nt][e] = 0.f;

    #pragma unroll
    for (int ks = 0; ks < 4; ks++) {
        const int kb = ks * 16 + 2 * tg;
        uint32_t a[4];
        a[0] = *(const uint32_t*)&Qh[(rq + gid) * KTP + kb];
        a[1] = *(const uint32_t*)&Qh[(rq + gid + 8) * KTP + kb];
        a[2] = *(const uint32_t*)&Qh[(rq + gid) * KTP + kb + 8];
        a[3] = *(const uint32_t*)&Qh[(rq + gid + 8) * KTP + kb + 8];
        #pragma unroll
        for (int nt = 0; nt < 24; nt++) {
            int n = nt * 8 + gid;
            uint32_t bfr[2];
            bfr[0] = *(const uint32_t*)&Kh[n * KTP + kb];
            bfr[1] = *(const uint32_t*)&Kh[n * KTP + kb + 8];
            mma_f16(acc[nt], a, bfr);
        }
    }

    // ---- mask + softmax in registers ----
    const int ql0 = rq + gid;      // rows ql0, ql0+8
    float m0 = -1e30f, m1 = -1e30f;
    #pragma unroll
    for (int nt = 0; nt < 24; nt++) {
        #pragma unroll
        for (int e = 0; e < 4; e++) {
            int col = nt * 8 + 2 * tg + (e & 1);
            int ql  = ql0 + ((e >> 1) << 3);
            float s = acc[nt][e] * 0.125f + pm[col];
            int d = col - ql - WIN;
            if (d > WIN || d < -WIN) s -= 10000.0f;
            acc[nt][e] = s;
            if (e < 2) m0 = fmaxf(m0, s); else m1 = fmaxf(m1, s);
        }
    }
    m0 = fmaxf(m0, __shfl_xor_sync(0xffffffffu, m0, 1));
    m0 = fmaxf(m0, __shfl_xor_sync(0xffffffffu, m0, 2));
    m1 = fmaxf(m1, __shfl_xor_sync(0xffffffffu, m1, 1));
    m1 = fmaxf(m1, __shfl_xor_sync(0xffffffffu, m1, 2));

    float s0 = 0.f, s1 = 0.f;
    #pragma unroll
    for (int nt = 0; nt < 24; nt++) {
        float e0 = expf(acc[nt][0] - m0);
        float e1 = expf(acc[nt][1] - m0);
        float e2 = expf(acc[nt][2] - m1);
        float e3 = expf(acc[nt][3] - m1);
        acc[nt][0] = e0; acc[nt][1] = e1; acc[nt][2] = e2; acc[nt][3] = e3;
        s0 += e0 + e1; s1 += e2 + e3;
    }
    s0 += __shfl_xor_sync(0xffffffffu, s0, 1);
    s0 += __shfl_xor_sync(0xffffffffu, s0, 2);
    s1 += __shfl_xor_sync(0xffffffffu, s1, 1);
    s1 += __shfl_xor_sync(0xffffffffu, s1, 2);
    const float inv0 = 1.0f / s0;
    const float inv1 = 1.0f / s1;

    // ---- PV: P (registers) x Vt ----
    float accV[8][4];
    #pragma unroll
    for (int nt = 0; nt < 8; nt++)
        #pragma unroll
        for (int e = 0; e < 4; e++) accV[nt][e] = 0.f;

    #pragma unroll
    for (int ks = 0; ks < 12; ks++) {
        uint32_t a[4];
        __half2 h0 = __floats2half2_rn(acc[2 * ks][0] * inv0,     acc[2 * ks][1] * inv0);
        __half2 h1 = __floats2half2_rn(acc[2 * ks][2] * inv1,     acc[2 * ks][3] * inv1);
        __half2 h2 = __floats2half2_rn(acc[2 * ks + 1][0] * inv0, acc[2 * ks + 1][1] * inv0);
        __half2 h3 = __floats2half2_rn(acc[2 * ks + 1][2] * inv1, acc[2 * ks + 1][3] * inv1);
        a[0] = *(uint32_t*)&h0;
        a[1] = *(uint32_t*)&h1;
        a[2] = *(uint32_t*)&h2;
        a[3] = *(uint32_t*)&h3;
        const int kb = ks * 16 + 2 * tg;
        #pragma unroll
        for (int nt = 0; nt < 8; nt++) {
            int n = nt * 8 + gid;      // d index
            uint32_t bfr[2];
            bfr[0] = *(const uint32_t*)&Vt[n * VTP + kb];
            bfr[1] = *(const uint32_t*)&Vt[n * VTP + kb + 8];
            mma_f16(accV[nt], a, bfr);
        }
    }

    // ---- store output (fp16, feeds w_o GEMM) ----
    #pragma unroll
    for (int nt = 0; nt < 8; nt++) {
        int col = h * DH_ + nt * 8 + 2 * tg;
        size_t r0 = (size_t)(b * S_ + qt0 + ql0) * DM_ + col;
        size_t r1 = (size_t)(b * S_ + qt0 + ql0 + 8) * DM_ + col;
        *(__half2*)&out[r0] = __floats2half2_rn(accV[nt][0], accV[nt][1]);
        *(__half2*)&out[r1] = __floats2half2_rn(accV[nt][2], accV[nt][3]);
    }
}

// ---------------- launch ----------------
extern "C" void kernel_launch(void* const* d_in, const int* in_sizes, int n_in,
                              void* d_out, int out_size) {
    const float* x          = (const float*)d_in[0];
    const int*   pmask      = (const int*)  d_in[1];
    const float* w_qkv      = (const float*)d_in[2];
    const float* w_o        = (const float*)d_in[3];
    const float* gamma_attn = (const float*)d_in[4];
    const float* gamma_mlp  = (const float*)d_in[5];
    const float* w_i0       = (const float*)d_in[6];
    const float* w_i1       = (const float*)d_in[7];
    const float* w_mo       = (const float*)d_in[8];
    float* out = (float*)d_out;

    __half *h, *attn, *act, *wqkv, *wo, *wi0, *wi1, *wmo;
    float *qkv, *x1, *gate;
    float2* ropeT;
    cudaGetSymbolAddress((void**)&h,    g_h);
    cudaGetSymbolAddress((void**)&qkv,  g_qkv);
    cudaGetSymbolAddress((void**)&attn, g_attn);
    cudaGetSymbolAddress((void**)&x1,   g_x1);
    cudaGetSymbolAddress((void**)&gate, g_gate);
    cudaGetSymbolAddress((void**)&act,  g_act);
    cudaGetSymbolAddress((void**)&ropeT, g_rope);
    cudaGetSymbolAddress((void**)&wqkv, g_wqkv);
    cudaGetSymbolAddress((void**)&wo,   g_wo);
    cudaGetSymbolAddress((void**)&wi0,  g_wi0);
    cudaGetSymbolAddress((void**)&wi1,  g_wi1);
    cudaGetSymbolAddress((void**)&wmo,  g_wmo);

    cudaFuncSetAttribute(mma_gemm_kernel,
                         cudaFuncAttributeMaxDynamicSharedMemorySize, GEMM_SMEM_BYTES);
    cudaFuncSetAttribute(attn_mma_kernel,
                         cudaFuncAttributeMaxDynamicSharedMemorySize, ATTN_SMEM_BYTES);

    dim3 tb(32, 8);
    wtransh_kernel<<<dim3(DM_ / 32, DQKV / 32), tb>>>(w_qkv, wqkv, DM_, DQKV);
    wtransh_kernel<<<dim3(DM_ / 32, DM_  / 32), tb>>>(w_o,   wo,   DM_, DM_);
    wtransh_kernel<<<dim3(DM_ / 32, DI_  / 32), tb>>>(w_i0,  wi0,  DM_, DI_);
    wtransh_kernel<<<dim3(DM_ / 32, DI_  / 32), tb>>>(w_i1,  wi1,  DM_, DI_);
    wtransh_kernel<<<dim3(DI_ / 32, DM_  / 32), tb>>>(w_mo,  wmo,  DI_, DM_);
    ropetab_kernel<<<(S_ * 32 + 255) / 256, 256>>>(ropeT);

    rmsnorm_kernel<<<ROWS, 256>>>(x, gamma_attn, h);
    mma_gemm_kernel<<<dim3(DQKV / BN, ROWS / BM), 256, GEMM_SMEM_BYTES>>>(
        h, wqkv, nullptr, qkv, ROWS, DQKV, DM_, 0);
    attn_mma_kernel<<<dim3(S_ / QT, H_, B_), 128, ATTN_SMEM_BYTES>>>(qkv, pmask, ropeT, attn);
    mma_gemm_kernel<<<dim3(DM_ / BN, ROWS / BM), 256, GEMM_SMEM_BYTES>>>(
        attn, wo, x, x1, ROWS, DM_, DM_, 1);
    rmsnorm_kernel<<<ROWS, 256>>>(x1, gamma_mlp, h);
    mma_gemm_kernel<<<dim3(DI_ / BN, ROWS / BM), 256, GEMM_SMEM_BYTES>>>(
        h, wi0, nullptr, gate, ROWS, DI_, DM_, 0);
    mma_gemm_kernel<<<dim3(DI_ / BN, ROWS / BM), 256, GEMM_SMEM_BYTES>>>(
        h, wi1, gate, act, ROWS, DI_, DM_, 2);
    mma_gemm_kernel<<<dim3(DM_ / BN, ROWS / BM), 256, GEMM_SMEM_BYTES>>>(
        act, wmo, x1, out, ROWS, DM_, DI_, 1);
}

// round 12
// speedup vs baseline: 2.2797x; 1.0645x over previous
#include <cuda_runtime.h>
#include <cuda_fp16.h>
#include <math.h>
#include <stdint.h>

// ---------------- problem constants ----------------
#define B_   2
#define S_   4096
#define DM_  768
#define DI_  1152
#define H_   12
#define DH_  64
#define ROWS (B_ * S_)          // 8192
#define DQKV (3 * DM_)          // 2304
#define WIN  64                 // WINDOW/2

// ---------------- scratch ----------------
__device__ __half g_h[ROWS * DM_];
__device__ float  g_qkv[ROWS * DQKV];
__device__ __half g_attn[ROWS * DM_];
__device__ float  g_x1[ROWS * DM_];
__device__ float  g_gate[ROWS * DI_];
__device__ __half g_act[ROWS * DI_];
__device__ float2 g_rope[S_ * 32];
__device__ __half g_wqkv[DQKV * DM_];
__device__ __half g_wo  [DM_ * DM_];
__device__ __half g_wi0 [DI_ * DM_];
__device__ __half g_wi1 [DI_ * DM_];
__device__ __half g_wmo [DM_ * DI_];

__device__ __forceinline__ float warpSum(float v) {
    #pragma unroll
    for (int o = 16; o; o >>= 1) v += __shfl_xor_sync(0xffffffffu, v, o);
    return v;
}

// ---------------- weight transpose + fp16 convert ----------------
__global__ void wtransh_kernel(const float* __restrict__ in, __half* __restrict__ out,
                               int K, int N) {
    __shared__ float t[32][33];
    int k0 = blockIdx.x * 32, n0 = blockIdx.y * 32;
    int tx = threadIdx.x, ty = threadIdx.y;
    #pragma unroll
    for (int i = ty; i < 32; i += 8)
        t[i][tx] = in[(size_t)(k0 + i) * N + n0 + tx];
    __syncthreads();
    #pragma unroll
    for (int i = ty; i < 32; i += 8)
        out[(size_t)(n0 + i) * K + k0 + tx] = __float2half_rn(t[tx][i]);
}

// ---------------- RoPE table ----------------
__global__ void ropetab_kernel(float2* __restrict__ tab) {
    int idx = blockIdx.x * blockDim.x + threadIdx.x;
    if (idx >= S_ * 32) return;
    int s = idx >> 5, d = idx & 31;
    float w = (float)(2 * d) / (float)DH_;
    float inv_freq = 1.0f / powf(10000.0f, w);
    float ang = (float)s * inv_freq;
    tab[idx] = make_float2(cosf(ang), sinf(ang));
}

// ---------------- RMSNorm (fp16 output) ----------------
__global__ void rmsnorm_kernel(const float* __restrict__ x,
                               const float* __restrict__ gamma,
                               __half* __restrict__ o) {
    int row = blockIdx.x;
    const float* xr = x + (size_t)row * DM_;
    float s = 0.f;
    for (int i = threadIdx.x; i < DM_; i += 256) { float v = xr[i]; s += v * v; }
    __shared__ float red[8];
    float w = warpSum(s);
    if ((threadIdx.x & 31) == 0) red[threadIdx.x >> 5] = w;
    __syncthreads();
    float tot = 0.f;
    #pragma unroll
    for (int i = 0; i < 8; i++) tot += red[i];
    float inv = rsqrtf(tot / (float)DM_ + 1e-5f);
    __half* orow = o + (size_t)row * DM_;
    for (int i = threadIdx.x; i < DM_; i += 256)
        orow[i] = __float2half_rn(xr[i] * inv * gamma[i]);
}

// =================== fp16 tensor-core GEMM (ldmatrix fragments) ====
#define BM 128
#define BN 128
#define BK 32
#define HSTRIDE 40
#define STAGE_HALVES ((BM + BN) * HSTRIDE)
#define STAGE_BYTES (STAGE_HALVES * 2)
#define NSTAGE 4
#define GEMM_SMEM_BYTES (NSTAGE * STAGE_BYTES)

__device__ __forceinline__ void mma_f16(float c[4], const uint32_t a[4], const uint32_t b[2]) {
    asm volatile(
        "mma.sync.aligned.m16n8k16.row.col.f32.f16.f16.f32 "
        "{%0,%1,%2,%3}, {%4,%5,%6,%7}, {%8,%9}, {%0,%1,%2,%3};"
        : "+f"(c[0]), "+f"(c[1]), "+f"(c[2]), "+f"(c[3])
        : "r"(a[0]), "r"(a[1]), "r"(a[2]), "r"(a[3]), "r"(b[0]), "r"(b[1]));
}

__device__ __forceinline__ void ldsm_x4(uint32_t r[4], uint32_t saddr) {
    asm volatile("ldmatrix.sync.aligned.m8n8.x4.shared.b16 {%0,%1,%2,%3}, [%4];"
        : "=r"(r[0]), "=r"(r[1]), "=r"(r[2]), "=r"(r[3]) : "r"(saddr));
}

__device__ __forceinline__ void cp16(const __half* dst_smem, const __half* src) {
    uint32_t d = (uint32_t)__cvta_generic_to_shared(dst_smem);
    asm volatile("cp.async.cg.shared.global [%0], [%1], 16;" :: "r"(d), "l"(src));
}

__device__ __forceinline__ float gelu_t(float x) {
    float t = tanhf(0.7978845608028654f * (x + 0.044715f * x * x * x));
    return 0.5f * x * (1.0f + t);
}

__global__ __launch_bounds__(256, 2)
void mma_gemm_kernel(const __half* __restrict__ A, const __half* __restrict__ Bt,
                     const float* __restrict__ Res, void* __restrict__ Cv,
                     int M, int N, int K, int mode) {
    extern __shared__ __half smh[];

    const int tid  = threadIdx.x;
    const int lane = tid & 31;
    const int warp = tid >> 5;
    const int gid  = lane >> 2;
    const int tg   = lane & 3;
    const int wm   = warp >> 1;
    const int wn   = warp & 1;

    const int bm = blockIdx.y * BM;
    const int bn = blockIdx.x * BN;

    // ldmatrix per-lane row/col offsets (halves)
    const uint32_t smBase = (uint32_t)__cvta_generic_to_shared(smh);
    const int rowA0 = wm * 32 + (lane & 15);                 // + mt*16
    const int koffA = (lane >> 4) << 3;
    const int rowB0 = wn * 64 + (lane & 7) + ((lane >> 4) << 3);  // + ntp*16
    const int koffB = ((lane >> 3) & 1) << 3;

    float acc[2][8][4];
    #pragma unroll
    for (int i = 0; i < 2; i++)
        #pragma unroll
        for (int j = 0; j < 8; j++)
            #pragma unroll
            for (int l = 0; l < 4; l++) acc[i][j][l] = 0.f;

    const int ntiles = K / BK;

    #define ISSUE_TILE(t, buf) do {                                            \
        __half* As_ = smh + (buf) * STAGE_HALVES;                               \
        __half* Bs_ = As_ + BM * HSTRIDE;                                       \
        int k0_ = (t) * BK;                                                     \
        _Pragma("unroll")                                                       \
        for (int u = 0; u < 2; u++) {                                           \
            int i = tid + u * 256;                                              \
            int r = i >> 2, c = i & 3;                                          \
            cp16(&As_[r * HSTRIDE + c * 8],                                     \
                 &A[(size_t)(bm + r) * K + k0_ + c * 8]);                       \
        }                                                                       \
        _Pragma("unroll")                                                       \
        for (int u = 0; u < 2; u++) {                                           \
            int i = tid + u * 256;                                              \
            int r = i >> 2, c = i & 3;                                          \
            cp16(&Bs_[r * HSTRIDE + c * 8],                                     \
                 &Bt[(size_t)(bn + r) * K + k0_ + c * 8]);                      \
        }                                                                       \
        asm volatile("cp.async.commit_group;");                                 \
    } while (0)

    ISSUE_TILE(0, 0);
    if (ntiles > 1) ISSUE_TILE(1, 1);
    if (ntiles > 2) ISSUE_TILE(2, 2);

    int buf = 0;
    for (int t = 0; t < ntiles; t++) {
        int rem = ntiles - 1 - t;
        if (rem >= 2)      asm volatile("cp.async.wait_group 2;");
        else if (rem == 1) asm volatile("cp.async.wait_group 1;");
        else               asm volatile("cp.async.wait_group 0;");
        __syncthreads();

        if (t + 3 < ntiles) {
            int nb = buf + 3; if (nb >= NSTAGE) nb -= NSTAGE;
            ISSUE_TILE(t + 3, nb);
        }

        const uint32_t aBase = smBase + buf * STAGE_BYTES;
        const uint32_t bBase = aBase + BM * HSTRIDE * 2;

        #pragma unroll
        for (int ks = 0; ks < 2; ks++) {
            uint32_t af[2][4], bf[8][2];
            #pragma unroll
            for (int mt = 0; mt < 2; mt++) {
                ldsm_x4(af[mt],
                        aBase + ((rowA0 + mt * 16) * HSTRIDE + ks * 16 + koffA) * 2);
            }
            #pragma unroll
            for (int ntp = 0; ntp < 4; ntp++) {
                uint32_t r[4];
                ldsm_x4(r, bBase + ((rowB0 + ntp * 16) * HSTRIDE + ks * 16 + koffB) * 2);
                bf[2 * ntp][0]     = r[0];
                bf[2 * ntp][1]     = r[1];
                bf[2 * ntp + 1][0] = r[2];
                bf[2 * ntp + 1][1] = r[3];
            }
            #pragma unroll
            for (int mt = 0; mt < 2; mt++)
                #pragma unroll
                for (int nt = 0; nt < 8; nt++)
                    mma_f16(acc[mt][nt], af[mt], bf[nt]);
        }

        buf++; if (buf >= NSTAGE) buf = 0;
    }

    #pragma unroll
    for (int mt = 0; mt < 2; mt++) {
        #pragma unroll
        for (int nt = 0; nt < 8; nt++) {
            int m0 = bm + wm * 32 + mt * 16 + gid;
            int n0 = bn + wn * 64 + nt * 8 + tg * 2;
            float2 v0 = make_float2(acc[mt][nt][0], acc[mt][nt][1]);
            float2 v1 = make_float2(acc[mt][nt][2], acc[mt][nt][3]);
            if (mode == 2) {
                float2 r0 = *(const float2*)&Res[(size_t)m0 * N + n0];
                float2 r1 = *(const float2*)&Res[(size_t)(m0 + 8) * N + n0];
                __half* Ch = (__half*)Cv;
                *(__half2*)&Ch[(size_t)m0 * N + n0] =
                    __floats2half2_rn(gelu_t(r0.x) * v0.x, gelu_t(r0.y) * v0.y);
                *(__half2*)&Ch[(size_t)(m0 + 8) * N + n0] =
                    __floats2half2_rn(gelu_t(r1.x) * v1.x, gelu_t(r1.y) * v1.y);
            } else {
                if (mode == 1) {
                    float2 r0 = *(const float2*)&Res[(size_t)m0 * N + n0];
                    float2 r1 = *(const float2*)&Res[(size_t)(m0 + 8) * N + n0];
                    v0.x += r0.x; v0.y += r0.y;
                    v1.x += r1.x; v1.y += r1.y;
                }
                float* C = (float*)Cv;
                *(float2*)&C[(size_t)m0 * N + n0] = v0;
                *(float2*)&C[(size_t)(m0 + 8) * N + n0] = v1;
            }
        }
    }
}

// =================== tensor-core sliding-window attention (R11) ====
#define QT 64
#define KT 192
#define KTP 72
#define VTP 200
#define ATTN_SMEM_BYTES ((QT * KTP + KT * KTP + DH_ * VTP) * 2 + KT * 4)

__device__ __forceinline__ void rope_h(const float2* __restrict__ tab, int s, int c,
                                       float4 lo, float4 hi, __half2 olo[2], __half2 ohi[2]) {
    float rlo[4], rhi[4];
    #pragma unroll
    for (int l = 0; l < 4; l++) {
        float2 cs = tab[s * 32 + c * 4 + l];
        float x1 = (&lo.x)[l];
        float x2 = (&hi.x)[l];
        rlo[l] = x1 * cs.x - x2 * cs.y;
        rhi[l] = x2 * cs.x + x1 * cs.y;
    }
    olo[0] = __floats2half2_rn(rlo[0], rlo[1]);
    olo[1] = __floats2half2_rn(rlo[2], rlo[3]);
    ohi[0] = __floats2half2_rn(rhi[0], rhi[1]);
    ohi[1] = __floats2half2_rn(rhi[2], rhi[3]);
}

__global__ __launch_bounds__(128)
void attn_mma_kernel(const float* __restrict__ qkv, const int* __restrict__ pmask,
                     const float2* __restrict__ ropeT, __half* __restrict__ out) {
    extern __shared__ __half smh[];
    __half* Qh = smh;
    __half* Kh = Qh + QT * KTP;
    __half* Vt = Kh + KT * KTP;
    float*  pm = (float*)(Vt + DH_ * VTP);

    const int qt0 = blockIdx.x * QT;
    const int h   = blockIdx.y;
    const int b   = blockIdx.z;
    const int tid = threadIdx.x;
    const int lane = tid & 31;
    const int warp = tid >> 5;
    const int gid  = lane >> 2;
    const int tg   = lane & 3;

    for (int i = tid; i < KT; i += 128) {
        int j = qt0 - WIN + i;
        pm[i] = (j < 0 || j >= S_) ? -1e30f : (pmask[b * S_ + j] ? 0.f : -10000.0f);
    }
    #pragma unroll
    for (int it = 0; it < 4; it++) {
        int i = tid + it * 128;
        int r = i >> 3, c = i & 7;
        int s = qt0 + r;
        size_t base = (size_t)(b * S_ + s) * DQKV + h * DH_;
        float4 lo = *(const float4*)&qkv[base + c * 4];
        float4 hi = *(const float4*)&qkv[base + 32 + c * 4];
        __half2 olo[2], ohi[2];
        rope_h(ropeT, s, c, lo, hi, olo, ohi);
        *(__half2*)&Qh[r * KTP + c * 4]      = olo[0];
        *(__half2*)&Qh[r * KTP + c * 4 + 2]  = olo[1];
        *(__half2*)&Qh[r * KTP + 32 + c * 4]     = ohi[0];
        *(__half2*)&Qh[r * KTP + 32 + c * 4 + 2] = ohi[1];
    }
    #pragma unroll
    for (int it = 0; it < 12; it++) {
        int i = tid + it * 128;
        int r = i >> 3, c = i & 7;
        int j = qt0 - WIN + r;
        __half2 olo[2], ohi[2];
        if (j >= 0 && j < S_) {
            size_t base = (size_t)(b * S_ + j) * DQKV + DM_ + h * DH_;
            float4 lo = *(const float4*)&qkv[base + c * 4];
            float4 hi = *(const float4*)&qkv[base + 32 + c * 4];
            rope_h(ropeT, j, c, lo, hi, olo, ohi);
        } else {
            olo[0] = olo[1] = ohi[0] = ohi[1] = __floats2half2_rn(0.f, 0.f);
        }
        *(__half2*)&Kh[r * KTP + c * 4]      = olo[0];
        *(__half2*)&Kh[r * KTP + c * 4 + 2]  = olo[1];
        *(__half2*)&Kh[r * KTP + 32 + c * 4]     = ohi[0];
        *(__half2*)&Kh[r * KTP + 32 + c * 4 + 2] = ohi[1];
    }
    #pragma unroll
    for (int it = 0; it < 24; it++) {
        int i = tid + it * 128;
        int r = i >> 4, c = i & 15;
        int j = qt0 - WIN + r;
        float4 v = make_float4(0.f, 0.f, 0.f, 0.f);
        if (j >= 0 && j < S_)
            v = *(const float4*)&qkv[(size_t)(b * S_ + j) * DQKV + 2 * DM_ + h * DH_ + c * 4];
        Vt[(c * 4 + 0) * VTP + r] = __float2half_rn(v.x);
        Vt[(c * 4 + 1) * VTP + r] = __float2half_rn(v.y);
        Vt[(c * 4 + 2) * VTP + r] = __float2half_rn(v.z);
        Vt[(c * 4 + 3) * VTP + r] = __float2half_rn(v.w);
    }
    __syncthreads();

    const int rq = warp * 16;
    float acc[24][4];
    #pragma unroll
    for (int nt = 0; nt < 24; nt++)
        #pragma unroll
        for (int e = 0; e < 4; e++) acc[nt][e] = 0.f;

    #pragma unroll
    for (int ks = 0; ks < 4; ks++) {
        const int kb = ks * 16 + 2 * tg;
        uint32_t a[4];
        a[0] = *(const uint32_t*)&Qh[(rq + gid) * KTP + kb];
        a[1] = *(const uint32_t*)&Qh[(rq + gid + 8) * KTP + kb];
        a[2] = *(const uint32_t*)&Qh[(rq + gid) * KTP + kb + 8];
        a[3] = *(const uint32_t*)&Qh[(rq + gid + 8) * KTP + kb + 8];
        #pragma unroll
        for (int nt = 0; nt < 24; nt++) {
            int n = nt * 8 + gid;
            uint32_t bfr[2];
            bfr[0] = *(const uint32_t*)&Kh[n * KTP + kb];
            bfr[1] = *(const uint32_t*)&Kh[n * KTP + kb + 8];
            mma_f16(acc[nt], a, bfr);
        }
    }

    const int ql0 = rq + gid;
    float m0 = -1e30f, m1 = -1e30f;
    #pragma unroll
    for (int nt = 0; nt < 24; nt++) {
        #pragma unroll
        for (int e = 0; e < 4; e++) {
            int col = nt * 8 + 2 * tg + (e & 1);
            int ql  = ql0 + ((e >> 1) << 3);
            float s = acc[nt][e] * 0.125f + pm[col];
            int d = col - ql - WIN;
            if (d > WIN || d < -WIN) s -= 10000.0f;
            acc[nt][e] = s;
            if (e < 2) m0 = fmaxf(m0, s); else m1 = fmaxf(m1, s);
        }
    }
    m0 = fmaxf(m0, __shfl_xor_sync(0xffffffffu, m0, 1));
    m0 = fmaxf(m0, __shfl_xor_sync(0xffffffffu, m0, 2));
    m1 = fmaxf(m1, __shfl_xor_sync(0xffffffffu, m1, 1));
    m1 = fmaxf(m1, __shfl_xor_sync(0xffffffffu, m1, 2));

    float s0 = 0.f, s1 = 0.f;
    #pragma unroll
    for (int nt = 0; nt < 24; nt++) {
        float e0 = expf(acc[nt][0] - m0);
        float e1 = expf(acc[nt][1] - m0);
        float e2 = expf(acc[nt][2] - m1);
        float e3 = expf(acc[nt][3] - m1);
        acc[nt][0] = e0; acc[nt][1] = e1; acc[nt][2] = e2; acc[nt][3] = e3;
        s0 += e0 + e1; s1 += e2 + e3;
    }
    s0 += __shfl_xor_sync(0xffffffffu, s0, 1);
    s0 += __shfl_xor_sync(0xffffffffu, s0, 2);
    s1 += __shfl_xor_sync(0xffffffffu, s1, 1);
    s1 += __shfl_xor_sync(0xffffffffu, s1, 2);
    const float inv0 = 1.0f / s0;
    const float inv1 = 1.0f / s1;

    float accV[8][4];
    #pragma unroll
    for (int nt = 0; nt < 8; nt++)
        #pragma unroll
        for (int e = 0; e < 4; e++) accV[nt][e] = 0.f;

    #pragma unroll
    for (int ks = 0; ks < 12; ks++) {
        uint32_t a[4];
        __half2 h0 = __floats2half2_rn(acc[2 * ks][0] * inv0,     acc[2 * ks][1] * inv0);
        __half2 h1 = __floats2half2_rn(acc[2 * ks][2] * inv1,     acc[2 * ks][3] * inv1);
        __half2 h2 = __floats2half2_rn(acc[2 * ks + 1][0] * inv0, acc[2 * ks + 1][1] * inv0);
        __half2 h3 = __floats2half2_rn(acc[2 * ks + 1][2] * inv1, acc[2 * ks + 1][3] * inv1);
        a[0] = *(uint32_t*)&h0;
        a[1] = *(uint32_t*)&h1;
        a[2] = *(uint32_t*)&h2;
        a[3] = *(uint32_t*)&h3;
        const int kb = ks * 16 + 2 * tg;
        #pragma unroll
        for (int nt = 0; nt < 8; nt++) {
            int n = nt * 8 + gid;
            uint32_t bfr[2];
            bfr[0] = *(const uint32_t*)&Vt[n * VTP + kb];
            bfr[1] = *(const uint32_t*)&Vt[n * VTP + kb + 8];
            mma_f16(accV[nt], a, bfr);
        }
    }

    #pragma unroll
    for (int nt = 0; nt < 8; nt++) {
        int col = h * DH_ + nt * 8 + 2 * tg;
        size_t r0 = (size_t)(b * S_ + qt0 + ql0) * DM_ + col;
        size_t r1 = (size_t)(b * S_ + qt0 + ql0 + 8) * DM_ + col;
        *(__half2*)&out[r0] = __floats2half2_rn(accV[nt][0], accV[nt][1]);
        *(__half2*)&out[r1] = __floats2half2_rn(accV[nt][2], accV[nt][3]);
    }
}

// ---------------- launch ----------------
extern "C" void kernel_launch(void* const* d_in, const int* in_sizes, int n_in,
                              void* d_out, int out_size) {
    const float* x          = (const float*)d_in[0];
    const int*   pmask      = (const int*)  d_in[1];
    const float* w_qkv      = (const float*)d_in[2];
    const float* w_o        = (const float*)d_in[3];
    const float* gamma_attn = (const float*)d_in[4];
    const float* gamma_mlp  = (const float*)d_in[5];
    const float* w_i0       = (const float*)d_in[6];
    const float* w_i1       = (const float*)d_in[7];
    const float* w_mo       = (const float*)d_in[8];
    float* out = (float*)d_out;

    __half *h, *attn, *act, *wqkv, *wo, *wi0, *wi1, *wmo;
    float *qkv, *x1, *gate;
    float2* ropeT;
    cudaGetSymbolAddress((void**)&h,    g_h);
    cudaGetSymbolAddress((void**)&qkv,  g_qkv);
    cudaGetSymbolAddress((void**)&attn, g_attn);
    cudaGetSymbolAddress((void**)&x1,   g_x1);
    cudaGetSymbolAddress((void**)&gate, g_gate);
    cudaGetSymbolAddress((void**)&act,  g_act);
    cudaGetSymbolAddress((void**)&ropeT, g_rope);
    cudaGetSymbolAddress((void**)&wqkv, g_wqkv);
    cudaGetSymbolAddress((void**)&wo,   g_wo);
    cudaGetSymbolAddress((void**)&wi0,  g_wi0);
    cudaGetSymbolAddress((void**)&wi1,  g_wi1);
    cudaGetSymbolAddress((void**)&wmo,  g_wmo);

    cudaFuncSetAttribute(mma_gemm_kernel,
                         cudaFuncAttributeMaxDynamicSharedMemorySize, GEMM_SMEM_BYTES);
    cudaFuncSetAttribute(attn_mma_kernel,
                         cudaFuncAttributeMaxDynamicSharedMemorySize, ATTN_SMEM_BYTES);

    dim3 tb(32, 8);
    wtransh_kernel<<<dim3(DM_ / 32, DQKV / 32), tb>>>(w_qkv, wqkv, DM_, DQKV);
    wtransh_kernel<<<dim3(DM_ / 32, DM_  / 32), tb>>>(w_o,   wo,   DM_, DM_);
    wtransh_kernel<<<dim3(DM_ / 32, DI_  / 32), tb>>>(w_i0,  wi0,  DM_, DI_);
    wtransh_kernel<<<dim3(DM_ / 32, DI_  / 32), tb>>>(w_i1,  wi1,  DM_, DI_);
    wtransh_kernel<<<dim3(DI_ / 32, DM_  / 32), tb>>>(w_mo,  wmo,  DI_, DM_);
    ropetab_kernel<<<(S_ * 32 + 255) / 256, 256>>>(ropeT);

    rmsnorm_kernel<<<ROWS, 256>>>(x, gamma_attn, h);
    mma_gemm_kernel<<<dim3(DQKV / BN, ROWS / BM), 256, GEMM_SMEM_BYTES>>>(
        h, wqkv, nullptr, qkv, ROWS, DQKV, DM_, 0);
    attn_mma_kernel<<<dim3(S_ / QT, H_, B_), 128, ATTN_SMEM_BYTES>>>(qkv, pmask, ropeT, attn);
    mma_gemm_kernel<<<dim3(DM_ / BN, ROWS / BM), 256, GEMM_SMEM_BYTES>>>(
        attn, wo, x, x1, ROWS, DM_, DM_, 1);
    rmsnorm_kernel<<<ROWS, 256>>>(x1, gamma_mlp, h);
    mma_gemm_kernel<<<dim3(DI_ / BN, ROWS / BM), 256, GEMM_SMEM_BYTES>>>(
        h, wi0, nullptr, gate, ROWS, DI_, DM_, 0);
    mma_gemm_kernel<<<dim3(DI_ / BN, ROWS / BM), 256, GEMM_SMEM_BYTES>>>(
        h, wi1, gate, act, ROWS, DI_, DM_, 2);
    mma_gemm_kernel<<<dim3(DM_ / BN, ROWS / BM), 256, GEMM_SMEM_BYTES>>>(
        act, wmo, x1, out, ROWS, DM_, DI_, 1);
}

// round 13
// speedup vs baseline: 2.5724x; 1.1284x over previous
#include <cuda_runtime.h>
#include <cuda_fp16.h>
#include <math.h>
#include <stdint.h>

// ---------------- problem constants ----------------
#define B_   2
#define S_   4096
#define DM_  768
#define DI_  1152
#define H_   12
#define DH_  64
#define ROWS (B_ * S_)          // 8192
#define DQKV (3 * DM_)          // 2304
#define WIN  64                 // WINDOW/2

// ---------------- scratch ----------------
__device__ __half g_h[ROWS * DM_];
__device__ float  g_qkv[ROWS * DQKV];
__device__ __half g_attn[ROWS * DM_];
__device__ float  g_x1[ROWS * DM_];
__device__ float  g_gate[ROWS * DI_];
__device__ __half g_act[ROWS * DI_];
__device__ float2 g_rope[S_ * 32];
__device__ __half g_wqkv[DQKV * DM_];
__device__ __half g_wo  [DM_ * DM_];
__device__ __half g_wi0 [DI_ * DM_];
__device__ __half g_wi1 [DI_ * DM_];
__device__ __half g_wmo [DM_ * DI_];

__device__ __forceinline__ float warpSum(float v) {
    #pragma unroll
    for (int o = 16; o; o >>= 1) v += __shfl_xor_sync(0xffffffffu, v, o);
    return v;
}

// ---------------- merged weight prep: transpose + fp16, all 5 weights ------
__global__ void wprep_kernel(const float* __restrict__ w_qkv, const float* __restrict__ w_o,
                             const float* __restrict__ w_i0,  const float* __restrict__ w_i1,
                             const float* __restrict__ w_mo,
                             __half* __restrict__ o_qkv, __half* __restrict__ o_o,
                             __half* __restrict__ o_i0,  __half* __restrict__ o_i1,
                             __half* __restrict__ o_mo) {
    const float* in; __half* out; int K, N;
    switch (blockIdx.z) {
        case 0: in = w_qkv; out = o_qkv; K = DM_; N = DQKV; break;
        case 1: in = w_o;   out = o_o;   K = DM_; N = DM_;  break;
        case 2: in = w_i0;  out = o_i0;  K = DM_; N = DI_;  break;
        case 3: in = w_i1;  out = o_i1;  K = DM_; N = DI_;  break;
        default:in = w_mo;  out = o_mo;  K = DI_; N = DM_;  break;
    }
    int k0 = blockIdx.x * 32, n0 = blockIdx.y * 32;
    if (k0 >= K || n0 >= N) return;
    __shared__ float t[32][33];
    int tx = threadIdx.x, ty = threadIdx.y;
    #pragma unroll
    for (int i = ty; i < 32; i += 8)
        t[i][tx] = in[(size_t)(k0 + i) * N + n0 + tx];
    __syncthreads();
    #pragma unroll
    for (int i = ty; i < 32; i += 8)
        out[(size_t)(n0 + i) * K + k0 + tx] = __float2half_rn(t[tx][i]);
}

// ---------------- RoPE table ----------------
__global__ void ropetab_kernel(float2* __restrict__ tab) {
    int idx = blockIdx.x * blockDim.x + threadIdx.x;
    if (idx >= S_ * 32) return;
    int s = idx >> 5, d = idx & 31;
    float w = (float)(2 * d) / (float)DH_;
    float inv_freq = 1.0f / powf(10000.0f, w);
    float ang = (float)s * inv_freq;
    tab[idx] = make_float2(cosf(ang), sinf(ang));
}

// ---------------- RMSNorm (vectorized, fp16 output) ----------------
__global__ void rmsnorm_kernel(const float* __restrict__ x,
                               const float* __restrict__ gamma,
                               __half* __restrict__ o) {
    int row = blockIdx.x;
    const float4* xr = (const float4*)(x + (size_t)row * DM_);
    const int tid = threadIdx.x;
    float4 v4 = make_float4(0.f, 0.f, 0.f, 0.f);
    if (tid < 192) v4 = xr[tid];
    float s = v4.x * v4.x + v4.y * v4.y + v4.z * v4.z + v4.w * v4.w;
    __shared__ float red[8];
    float w = warpSum(s);
    if ((tid & 31) == 0) red[tid >> 5] = w;
    __syncthreads();
    float tot = 0.f;
    #pragma unroll
    for (int i = 0; i < 8; i++) tot += red[i];
    float inv = rsqrtf(tot / (float)DM_ + 1e-5f);
    if (tid < 192) {
        float4 g4 = ((const float4*)gamma)[tid];
        __half2 h0 = __floats2half2_rn(v4.x * inv * g4.x, v4.y * inv * g4.y);
        __half2 h1 = __floats2half2_rn(v4.z * inv * g4.z, v4.w * inv * g4.w);
        __half* orow = o + (size_t)row * DM_;
        *(__half2*)&orow[tid * 4]     = h0;
        *(__half2*)&orow[tid * 4 + 2] = h1;
    }
}

// =================== fp16 tensor-core GEMM: 128x128x64, 3-stage, ldmatrix ===
#define BM 128
#define BN 128
#define BK 64
#define HSTRIDE 72
#define STAGE_HALVES ((BM + BN) * HSTRIDE)           // 18432
#define STAGE_BYTES (STAGE_HALVES * 2)                // 36864
#define NSTAGE 3
#define GEMM_SMEM_BYTES (NSTAGE * STAGE_BYTES)        // 110592

__device__ __forceinline__ void mma_f16(float c[4], const uint32_t a[4], const uint32_t b[2]) {
    asm volatile(
        "mma.sync.aligned.m16n8k16.row.col.f32.f16.f16.f32 "
        "{%0,%1,%2,%3}, {%4,%5,%6,%7}, {%8,%9}, {%0,%1,%2,%3};"
        : "+f"(c[0]), "+f"(c[1]), "+f"(c[2]), "+f"(c[3])
        : "r"(a[0]), "r"(a[1]), "r"(a[2]), "r"(a[3]), "r"(b[0]), "r"(b[1]));
}

__device__ __forceinline__ void ldsm_x4(uint32_t r[4], uint32_t saddr) {
    asm volatile("ldmatrix.sync.aligned.m8n8.x4.shared.b16 {%0,%1,%2,%3}, [%4];"
        : "=r"(r[0]), "=r"(r[1]), "=r"(r[2]), "=r"(r[3]) : "r"(saddr));
}

__device__ __forceinline__ void cp16(const __half* dst_smem, const __half* src) {
    uint32_t d = (uint32_t)__cvta_generic_to_shared(dst_smem);
    asm volatile("cp.async.cg.shared.global [%0], [%1], 16;" :: "r"(d), "l"(src));
}

__device__ __forceinline__ float gelu_t(float x) {
    float t = tanhf(0.7978845608028654f * (x + 0.044715f * x * x * x));
    return 0.5f * x * (1.0f + t);
}

__global__ __launch_bounds__(256, 2)
void mma_gemm_kernel(const __half* __restrict__ A, const __half* __restrict__ Bt,
                     const float* __restrict__ Res, void* __restrict__ Cv,
                     int M, int N, int K, int mode) {
    extern __shared__ __half smh[];

    const int tid  = threadIdx.x;
    const int lane = tid & 31;
    const int warp = tid >> 5;
    const int gid  = lane >> 2;
    const int tg   = lane & 3;
    const int wm   = warp >> 1;
    const int wn   = warp & 1;

    const int bm = blockIdx.y * BM;
    const int bn = blockIdx.x * BN;

    const uint32_t smBase = (uint32_t)__cvta_generic_to_shared(smh);
    const int rowA0 = wm * 32 + (lane & 15);
    const int koffA = (lane >> 4) << 3;
    const int rowB0 = wn * 64 + (lane & 7) + ((lane >> 4) << 3);
    const int koffB = ((lane >> 3) & 1) << 3;

    float acc[2][8][4];
    #pragma unroll
    for (int i = 0; i < 2; i++)
        #pragma unroll
        for (int j = 0; j < 8; j++)
            #pragma unroll
            for (int l = 0; l < 4; l++) acc[i][j][l] = 0.f;

    const int ntiles = K / BK;

    // tile: A 128x64 halves = 1024 16B-chunks; B same; 256 thr -> 4+4 cp16
    #define ISSUE_TILE(t, buf) do {                                            \
        __half* As_ = smh + (buf) * STAGE_HALVES;                               \
        __half* Bs_ = As_ + BM * HSTRIDE;                                       \
        int k0_ = (t) * BK;                                                     \
        _Pragma("unroll")                                                       \
        for (int u = 0; u < 4; u++) {                                           \
            int i = tid + u * 256;                                              \
            int r = i >> 3, c = i & 7;                                          \
            cp16(&As_[r * HSTRIDE + c * 8],                                     \
                 &A[(size_t)(bm + r) * K + k0_ + c * 8]);                       \
        }                                                                       \
        _Pragma("unroll")                                                       \
        for (int u = 0; u < 4; u++) {                                           \
            int i = tid + u * 256;                                              \
            int r = i >> 3, c = i & 7;                                          \
            cp16(&Bs_[r * HSTRIDE + c * 8],                                     \
                 &Bt[(size_t)(bn + r) * K + k0_ + c * 8]);                      \
        }                                                                       \
        asm volatile("cp.async.commit_group;");                                 \
    } while (0)

    ISSUE_TILE(0, 0);
    if (ntiles > 1) ISSUE_TILE(1, 1);

    int buf = 0;
    for (int t = 0; t < ntiles; t++) {
        if (t + 1 < ntiles) asm volatile("cp.async.wait_group 1;");
        else                asm volatile("cp.async.wait_group 0;");
        __syncthreads();

        if (t + 2 < ntiles) {
            int nb = buf + 2; if (nb >= NSTAGE) nb -= NSTAGE;
            ISSUE_TILE(t + 2, nb);
        }

        const uint32_t aBase = smBase + buf * STAGE_BYTES;
        const uint32_t bBase = aBase + BM * HSTRIDE * 2;

        #pragma unroll
        for (int ks = 0; ks < 4; ks++) {
            uint32_t af[2][4], bf[8][2];
            #pragma unroll
            for (int mt = 0; mt < 2; mt++) {
                ldsm_x4(af[mt],
                        aBase + ((rowA0 + mt * 16) * HSTRIDE + ks * 16 + koffA) * 2);
            }
            #pragma unroll
            for (int ntp = 0; ntp < 4; ntp++) {
                uint32_t r[4];
                ldsm_x4(r, bBase + ((rowB0 + ntp * 16) * HSTRIDE + ks * 16 + koffB) * 2);
                bf[2 * ntp][0]     = r[0];
                bf[2 * ntp][1]     = r[1];
                bf[2 * ntp + 1][0] = r[2];
                bf[2 * ntp + 1][1] = r[3];
            }
            #pragma unroll
            for (int mt = 0; mt < 2; mt++)
                #pragma unroll
                for (int nt = 0; nt < 8; nt++)
                    mma_f16(acc[mt][nt], af[mt], bf[nt]);
        }

        buf++; if (buf >= NSTAGE) buf = 0;
    }

    #pragma unroll
    for (int mt = 0; mt < 2; mt++) {
        #pragma unroll
        for (int nt = 0; nt < 8; nt++) {
            int m0 = bm + wm * 32 + mt * 16 + gid;
            int n0 = bn + wn * 64 + nt * 8 + tg * 2;
            float2 v0 = make_float2(acc[mt][nt][0], acc[mt][nt][1]);
            float2 v1 = make_float2(acc[mt][nt][2], acc[mt][nt][3]);
            if (mode == 2) {
                float2 r0 = *(const float2*)&Res[(size_t)m0 * N + n0];
                float2 r1 = *(const float2*)&Res[(size_t)(m0 + 8) * N + n0];
                __half* Ch = (__half*)Cv;
                *(__half2*)&Ch[(size_t)m0 * N + n0] =
                    __floats2half2_rn(gelu_t(r0.x) * v0.x, gelu_t(r0.y) * v0.y);
                *(__half2*)&Ch[(size_t)(m0 + 8) * N + n0] =
                    __floats2half2_rn(gelu_t(r1.x) * v1.x, gelu_t(r1.y) * v1.y);
            } else {
                if (mode == 1) {
                    float2 r0 = *(const float2*)&Res[(size_t)m0 * N + n0];
                    float2 r1 = *(const float2*)&Res[(size_t)(m0 + 8) * N + n0];
                    v0.x += r0.x; v0.y += r0.y;
                    v1.x += r1.x; v1.y += r1.y;
                }
                float* C = (float*)Cv;
                *(float2*)&C[(size_t)m0 * N + n0] = v0;
                *(float2*)&C[(size_t)(m0 + 8) * N + n0] = v1;
            }
        }
    }
}

// =================== tensor-core sliding-window attention (R11/R12) ====
#define QT 64
#define KT 192
#define KTP 72
#define VTP 200
#define ATTN_SMEM_BYTES ((QT * KTP + KT * KTP + DH_ * VTP) * 2 + KT * 4)

__device__ __forceinline__ void rope_h(const float2* __restrict__ tab, int s, int c,
                                       float4 lo, float4 hi, __half2 olo[2], __half2 ohi[2]) {
    float rlo[4], rhi[4];
    #pragma unroll
    for (int l = 0; l < 4; l++) {
        float2 cs = tab[s * 32 + c * 4 + l];
        float x1 = (&lo.x)[l];
        float x2 = (&hi.x)[l];
        rlo[l] = x1 * cs.x - x2 * cs.y;
        rhi[l] = x2 * cs.x + x1 * cs.y;
    }
    olo[0] = __floats2half2_rn(rlo[0], rlo[1]);
    olo[1] = __floats2half2_rn(rlo[2], rlo[3]);
    ohi[0] = __floats2half2_rn(rhi[0], rhi[1]);
    ohi[1] = __floats2half2_rn(rhi[2], rhi[3]);
}

__global__ __launch_bounds__(128)
void attn_mma_kernel(const float* __restrict__ qkv, const int* __restrict__ pmask,
                     const float2* __restrict__ ropeT, __half* __restrict__ out) {
    extern __shared__ __half smh[];
    __half* Qh = smh;
    __half* Kh = Qh + QT * KTP;
    __half* Vt = Kh + KT * KTP;
    float*  pm = (float*)(Vt + DH_ * VTP);

    const int qt0 = blockIdx.x * QT;
    const int h   = blockIdx.y;
    const int b   = blockIdx.z;
    const int tid = threadIdx.x;
    const int lane = tid & 31;
    const int warp = tid >> 5;
    const int gid  = lane >> 2;
    const int tg   = lane & 3;

    for (int i = tid; i < KT; i += 128) {
        int j = qt0 - WIN + i;
        pm[i] = (j < 0 || j >= S_) ? -1e30f : (pmask[b * S_ + j] ? 0.f : -10000.0f);
    }
    #pragma unroll
    for (int it = 0; it < 4; it++) {
        int i = tid + it * 128;
        int r = i >> 3, c = i & 7;
        int s = qt0 + r;
        size_t base = (size_t)(b * S_ + s) * DQKV + h * DH_;
        float4 lo = *(const float4*)&qkv[base + c * 4];
        float4 hi = *(const float4*)&qkv[base + 32 + c * 4];
        __half2 olo[2], ohi[2];
        rope_h(ropeT, s, c, lo, hi, olo, ohi);
        *(__half2*)&Qh[r * KTP + c * 4]      = olo[0];
        *(__half2*)&Qh[r * KTP + c * 4 + 2]  = olo[1];
        *(__half2*)&Qh[r * KTP + 32 + c * 4]     = ohi[0];
        *(__half2*)&Qh[r * KTP + 32 + c * 4 + 2] = ohi[1];
    }
    #pragma unroll
    for (int it = 0; it < 12; it++) {
        int i = tid + it * 128;
        int r = i >> 3, c = i & 7;
        int j = qt0 - WIN + r;
        __half2 olo[2], ohi[2];
        if (j >= 0 && j < S_) {
            size_t base = (size_t)(b * S_ + j) * DQKV + DM_ + h * DH_;
            float4 lo = *(const float4*)&qkv[base + c * 4];
            float4 hi = *(const float4*)&qkv[base + 32 + c * 4];
            rope_h(ropeT, j, c, lo, hi, olo, ohi);
        } else {
            olo[0] = olo[1] = ohi[0] = ohi[1] = __floats2half2_rn(0.f, 0.f);
        }
        *(__half2*)&Kh[r * KTP + c * 4]      = olo[0];
        *(__half2*)&Kh[r * KTP + c * 4 + 2]  = olo[1];
        *(__half2*)&Kh[r * KTP + 32 + c * 4]     = ohi[0];
        *(__half2*)&Kh[r * KTP + 32 + c * 4 + 2] = ohi[1];
    }
    #pragma unroll
    for (int it = 0; it < 24; it++) {
        int i = tid + it * 128;
        int r = i >> 4, c = i & 15;
        int j = qt0 - WIN + r;
        float4 v = make_float4(0.f, 0.f, 0.f, 0.f);
        if (j >= 0 && j < S_)
            v = *(const float4*)&qkv[(size_t)(b * S_ + j) * DQKV + 2 * DM_ + h * DH_ + c * 4];
        Vt[(c * 4 + 0) * VTP + r] = __float2half_rn(v.x);
        Vt[(c * 4 + 1) * VTP + r] = __float2half_rn(v.y);
        Vt[(c * 4 + 2) * VTP + r] = __float2half_rn(v.z);
        Vt[(c * 4 + 3) * VTP + r] = __float2half_rn(v.w);
    }
    __syncthreads();

    const int rq = warp * 16;
    float acc[24][4];
    #pragma unroll
    for (int nt = 0; nt < 24; nt++)
        #pragma unroll
        for (int e = 0; e < 4; e++) acc[nt][e] = 0.f;

    #pragma unroll
    for (int ks = 0; ks < 4; ks++) {
        const int kb = ks * 16 + 2 * tg;
        uint32_t a[4];
        a[0] = *(const uint32_t*)&Qh[(rq + gid) * KTP + kb];
        a[1] = *(const uint32_t*)&Qh[(rq + gid + 8) * KTP + kb];
        a[2] = *(const uint32_t*)&Qh[(rq + gid) * KTP + kb + 8];
        a[3] = *(const uint32_t*)&Qh[(rq + gid + 8) * KTP + kb + 8];
        #pragma unroll
        for (int nt = 0; nt < 24; nt++) {
            int n = nt * 8 + gid;
            uint32_t bfr[2];
            bfr[0] = *(const uint32_t*)&Kh[n * KTP + kb];
            bfr[1] = *(const uint32_t*)&Kh[n * KTP + kb + 8];
            mma_f16(acc[nt], a, bfr);
        }
    }

    const int ql0 = rq + gid;
    float m0 = -1e30f, m1 = -1e30f;
    #pragma unroll
    for (int nt = 0; nt < 24; nt++) {
        #pragma unroll
        for (int e = 0; e < 4; e++) {
            int col = nt * 8 + 2 * tg + (e & 1);
            int ql  = ql0 + ((e >> 1) << 3);
            float s = acc[nt][e] * 0.125f + pm[col];
            int d = col - ql - WIN;
            if (d > WIN || d < -WIN) s -= 10000.0f;
            acc[nt][e] = s;
            if (e < 2) m0 = fmaxf(m0, s); else m1 = fmaxf(m1, s);
        }
    }
    m0 = fmaxf(m0, __shfl_xor_sync(0xffffffffu, m0, 1));
    m0 = fmaxf(m0, __shfl_xor_sync(0xffffffffu, m0, 2));
    m1 = fmaxf(m1, __shfl_xor_sync(0xffffffffu, m1, 1));
    m1 = fmaxf(m1, __shfl_xor_sync(0xffffffffu, m1, 2));

    float s0 = 0.f, s1 = 0.f;
    #pragma unroll
    for (int nt = 0; nt < 24; nt++) {
        float e0 = expf(acc[nt][0] - m0);
        float e1 = expf(acc[nt][1] - m0);
        float e2 = expf(acc[nt][2] - m1);
        float e3 = expf(acc[nt][3] - m1);
        acc[nt][0] = e0; acc[nt][1] = e1; acc[nt][2] = e2; acc[nt][3] = e3;
        s0 += e0 + e1; s1 += e2 + e3;
    }
    s0 += __shfl_xor_sync(0xffffffffu, s0, 1);
    s0 += __shfl_xor_sync(0xffffffffu, s0, 2);
    s1 += __shfl_xor_sync(0xffffffffu, s1, 1);
    s1 += __shfl_xor_sync(0xffffffffu, s1, 2);
    const float inv0 = 1.0f / s0;
    const float inv1 = 1.0f / s1;

    float accV[8][4];
    #pragma unroll
    for (int nt = 0; nt < 8; nt++)
        #pragma unroll
        for (int e = 0; e < 4; e++) accV[nt][e] = 0.f;

    #pragma unroll
    for (int ks = 0; ks < 12; ks++) {
        uint32_t a[4];
        __half2 h0 = __floats2half2_rn(acc[2 * ks][0] * inv0,     acc[2 * ks][1] * inv0);
        __half2 h1 = __floats2half2_rn(acc[2 * ks][2] * inv1,     acc[2 * ks][3] * inv1);
        __half2 h2 = __floats2half2_rn(acc[2 * ks + 1][0] * inv0, acc[2 * ks + 1][1] * inv0);
        __half2 h3 = __floats2half2_rn(acc[2 * ks + 1][2] * inv1, acc[2 * ks + 1][3] * inv1);
        a[0] = *(uint32_t*)&h0;
        a[1] = *(uint32_t*)&h1;
        a[2] = *(uint32_t*)&h2;
        a[3] = *(uint32_t*)&h3;
        const int kb = ks * 16 + 2 * tg;
        #pragma unroll
        for (int nt = 0; nt < 8; nt++) {
            int n = nt * 8 + gid;
            uint32_t bfr[2];
            bfr[0] = *(const uint32_t*)&Vt[n * VTP + kb];
            bfr[1] = *(const uint32_t*)&Vt[n * VTP + kb + 8];
            mma_f16(accV[nt], a, bfr);
        }
    }

    #pragma unroll
    for (int nt = 0; nt < 8; nt++) {
        int col = h * DH_ + nt * 8 + 2 * tg;
        size_t r0 = (size_t)(b * S_ + qt0 + ql0) * DM_ + col;
        size_t r1 = (size_t)(b * S_ + qt0 + ql0 + 8) * DM_ + col;
        *(__half2*)&out[r0] = __floats2half2_rn(accV[nt][0], accV[nt][1]);
        *(__half2*)&out[r1] = __floats2half2_rn(accV[nt][2], accV[nt][3]);
    }
}

// ---------------- launch ----------------
extern "C" void kernel_launch(void* const* d_in, const int* in_sizes, int n_in,
                              void* d_out, int out_size) {
    const float* x          = (const float*)d_in[0];
    const int*   pmask      = (const int*)  d_in[1];
    const float* w_qkv      = (const float*)d_in[2];
    const float* w_o        = (const float*)d_in[3];
    const float* gamma_attn = (const float*)d_in[4];
    const float* gamma_mlp  = (const float*)d_in[5];
    const float* w_i0       = (const float*)d_in[6];
    const float* w_i1       = (const float*)d_in[7];
    const float* w_mo       = (const float*)d_in[8];
    float* out = (float*)d_out;

    __half *h, *attn, *act, *wqkv, *wo, *wi0, *wi1, *wmo;
    float *qkv, *x1, *gate;
    float2* ropeT;
    cudaGetSymbolAddress((void**)&h,    g_h);
    cudaGetSymbolAddress((void**)&qkv,  g_qkv);
    cudaGetSymbolAddress((void**)&attn, g_attn);
    cudaGetSymbolAddress((void**)&x1,   g_x1);
    cudaGetSymbolAddress((void**)&gate, g_gate);
    cudaGetSymbolAddress((void**)&act,  g_act);
    cudaGetSymbolAddress((void**)&ropeT, g_rope);
    cudaGetSymbolAddress((void**)&wqkv, g_wqkv);
    cudaGetSymbolAddress((void**)&wo,   g_wo);
    cudaGetSymbolAddress((void**)&wi0,  g_wi0);
    cudaGetSymbolAddress((void**)&wi1,  g_wi1);
    cudaGetSymbolAddress((void**)&wmo,  g_wmo);

    cudaFuncSetAttribute(mma_gemm_kernel,
                         cudaFuncAttributeMaxDynamicSharedMemorySize, GEMM_SMEM_BYTES);
    cudaFuncSetAttribute(attn_mma_kernel,
                         cudaFuncAttributeMaxDynamicSharedMemorySize, ATTN_SMEM_BYTES);

    // one merged prep launch (z selects weight; OOB tiles early-exit)
    wprep_kernel<<<dim3(DI_ / 32, DQKV / 32, 5), dim3(32, 8)>>>(
        w_qkv, w_o, w_i0, w_i1, w_mo, wqkv, wo, wi0, wi1, wmo);
    ropetab_kernel<<<(S_ * 32 + 255) / 256, 256>>>(ropeT);

    rmsnorm_kernel<<<ROWS, 256>>>(x, gamma_attn, h);
    mma_gemm_kernel<<<dim3(DQKV / BN, ROWS / BM), 256, GEMM_SMEM_BYTES>>>(
        h, wqkv, nullptr, qkv, ROWS, DQKV, DM_, 0);
    attn_mma_kernel<<<dim3(S_ / QT, H_, B_), 128, ATTN_SMEM_BYTES>>>(qkv, pmask, ropeT, attn);
    mma_gemm_kernel<<<dim3(DM_ / BN, ROWS / BM), 256, GEMM_SMEM_BYTES>>>(
        attn, wo, x, x1, ROWS, DM_, DM_, 1);
    rmsnorm_kernel<<<ROWS, 256>>>(x1, gamma_mlp, h);
    mma_gemm_kernel<<<dim3(DI_ / BN, ROWS / BM), 256, GEMM_SMEM_BYTES>>>(
        h, wi0, nullptr, gate, ROWS, DI_, DM_, 0);
    mma_gemm_kernel<<<dim3(DI_ / BN, ROWS / BM), 256, GEMM_SMEM_BYTES>>>(
        h, wi1, gate, act, ROWS, DI_, DM_, 2);
    mma_gemm_kernel<<<dim3(DM_ / BN, ROWS / BM), 256, GEMM_SMEM_BYTES>>>(
        act, wmo, x1, out, ROWS, DM_, DI_, 1);
}

// round 14
// speedup vs baseline: 2.6540x; 1.0317x over previous
#include <cuda_runtime.h>
#include <cuda_fp16.h>
#include <math.h>
#include <stdint.h>

// ---------------- problem constants ----------------
#define B_   2
#define S_   4096
#define DM_  768
#define DI_  1152
#define H_   12
#define DH_  64
#define ROWS (B_ * S_)          // 8192
#define DQKV (3 * DM_)          // 2304
#define WIN  64                 // WINDOW/2

// ---------------- scratch ----------------
__device__ __half g_h[ROWS * DM_];
__device__ float  g_qkv[ROWS * DQKV];
__device__ __half g_attn[ROWS * DM_];
__device__ float  g_x1[ROWS * DM_];
__device__ __half g_act[ROWS * DI_];
__device__ float2 g_rope[S_ * 32];
__device__ __half g_wqkv[DQKV * DM_];
__device__ __half g_wo  [DM_ * DM_];
__device__ __half g_wi01[2 * DI_ * DM_];   // interleaved gate/up, [2304][768]
__device__ __half g_wmo [DM_ * DI_];

__device__ __forceinline__ float warpSum(float v) {
    #pragma unroll
    for (int o = 16; o; o >>= 1) v += __shfl_xor_sync(0xffffffffu, v, o);
    return v;
}

// ---------------- merged weight prep ----------------
// z=0: wqkv ; z=1: wo ; z=2: wi0 -> wi01 even groups ; z=3: wi1 -> wi01 odd ; z=4: wmo
__global__ void wprep_kernel(const float* __restrict__ w_qkv, const float* __restrict__ w_o,
                             const float* __restrict__ w_i0,  const float* __restrict__ w_i1,
                             const float* __restrict__ w_mo,
                             __half* __restrict__ o_qkv, __half* __restrict__ o_o,
                             __half* __restrict__ o_i01, __half* __restrict__ o_mo) {
    const float* in; __half* out; int K, N, mapMode;
    switch (blockIdx.z) {
        case 0: in = w_qkv; out = o_qkv; K = DM_; N = DQKV; mapMode = 0; break;
        case 1: in = w_o;   out = o_o;   K = DM_; N = DM_;  mapMode = 0; break;
        case 2: in = w_i0;  out = o_i01; K = DM_; N = DI_;  mapMode = 1; break;
        case 3: in = w_i1;  out = o_i01; K = DM_; N = DI_;  mapMode = 2; break;
        default:in = w_mo;  out = o_mo;  K = DI_; N = DM_;  mapMode = 0; break;
    }
    int k0 = blockIdx.x * 32, n0 = blockIdx.y * 32;
    if (k0 >= K || n0 >= N) return;
    __shared__ float t[32][33];
    int tx = threadIdx.x, ty = threadIdx.y;
    #pragma unroll
    for (int i = ty; i < 32; i += 8)
        t[i][tx] = in[(size_t)(k0 + i) * N + n0 + tx];
    __syncthreads();
    #pragma unroll
    for (int i = ty; i < 32; i += 8) {
        int n = n0 + i;
        int row;
        if (mapMode == 0)      row = n;
        else if (mapMode == 1) row = ((n >> 3) << 4) + (n & 7);
        else                   row = ((n >> 3) << 4) + 8 + (n & 7);
        out[(size_t)row * K + k0 + tx] = __float2half_rn(t[tx][i]);
    }
}

// ---------------- RoPE table ----------------
__global__ void ropetab_kernel(float2* __restrict__ tab) {
    int idx = blockIdx.x * blockDim.x + threadIdx.x;
    if (idx >= S_ * 32) return;
    int s = idx >> 5, d = idx & 31;
    float w = (float)(2 * d) / (float)DH_;
    float inv_freq = 1.0f / powf(10000.0f, w);
    float ang = (float)s * inv_freq;
    tab[idx] = make_float2(cosf(ang), sinf(ang));
}

// ---------------- RMSNorm (vectorized, fp16 output) ----------------
__global__ void rmsnorm_kernel(const float* __restrict__ x,
                               const float* __restrict__ gamma,
                               __half* __restrict__ o) {
    int row = blockIdx.x;
    const float4* xr = (const float4*)(x + (size_t)row * DM_);
    const int tid = threadIdx.x;
    float4 v4 = make_float4(0.f, 0.f, 0.f, 0.f);
    if (tid < 192) v4 = xr[tid];
    float s = v4.x * v4.x + v4.y * v4.y + v4.z * v4.z + v4.w * v4.w;
    __shared__ float red[8];
    float w = warpSum(s);
    if ((tid & 31) == 0) red[tid >> 5] = w;
    __syncthreads();
    float tot = 0.f;
    #pragma unroll
    for (int i = 0; i < 8; i++) tot += red[i];
    float inv = rsqrtf(tot / (float)DM_ + 1e-5f);
    if (tid < 192) {
        float4 g4 = ((const float4*)gamma)[tid];
        __half2 h0 = __floats2half2_rn(v4.x * inv * g4.x, v4.y * inv * g4.y);
        __half2 h1 = __floats2half2_rn(v4.z * inv * g4.z, v4.w * inv * g4.w);
        __half* orow = o + (size_t)row * DM_;
        *(__half2*)&orow[tid * 4]     = h0;
        *(__half2*)&orow[tid * 4 + 2] = h1;
    }
}

// =================== fp16 tensor-core GEMM: 128x128x64, 3-stage, ldmatrix ===
// mode 0: C=acc(f32) ; 1: C=Res+acc(f32) ; 2: unused ; 3: fused gate/up ->
//   act[m][(n>>4)*8+(n&7)] = h(gelu(acc_even)*acc_odd)  (N must be 2*DI_)
#define BM 128
#define BN 128
#define BK 64
#define HSTRIDE 72
#define STAGE_HALVES ((BM + BN) * HSTRIDE)
#define STAGE_BYTES (STAGE_HALVES * 2)
#define NSTAGE 3
#define GEMM_SMEM_BYTES (NSTAGE * STAGE_BYTES)

__device__ __forceinline__ void mma_f16(float c[4], const uint32_t a[4], const uint32_t b[2]) {
    asm volatile(
        "mma.sync.aligned.m16n8k16.row.col.f32.f16.f16.f32 "
        "{%0,%1,%2,%3}, {%4,%5,%6,%7}, {%8,%9}, {%0,%1,%2,%3};"
        : "+f"(c[0]), "+f"(c[1]), "+f"(c[2]), "+f"(c[3])
        : "r"(a[0]), "r"(a[1]), "r"(a[2]), "r"(a[3]), "r"(b[0]), "r"(b[1]));
}

__device__ __forceinline__ void ldsm_x4(uint32_t r[4], uint32_t saddr) {
    asm volatile("ldmatrix.sync.aligned.m8n8.x4.shared.b16 {%0,%1,%2,%3}, [%4];"
        : "=r"(r[0]), "=r"(r[1]), "=r"(r[2]), "=r"(r[3]) : "r"(saddr));
}

__device__ __forceinline__ void cp16(const __half* dst_smem, const __half* src) {
    uint32_t d = (uint32_t)__cvta_generic_to_shared(dst_smem);
    asm volatile("cp.async.cg.shared.global [%0], [%1], 16;" :: "r"(d), "l"(src));
}

__device__ __forceinline__ float gelu_t(float x) {
    float t = tanhf(0.7978845608028654f * (x + 0.044715f * x * x * x));
    return 0.5f * x * (1.0f + t);
}

__global__ __launch_bounds__(256, 2)
void mma_gemm_kernel(const __half* __restrict__ A, const __half* __restrict__ Bt,
                     const float* __restrict__ Res, void* __restrict__ Cv,
                     int M, int N, int K, int mode) {
    extern __shared__ __half smh[];

    const int tid  = threadIdx.x;
    const int lane = tid & 31;
    const int warp = tid >> 5;
    const int gid  = lane >> 2;
    const int tg   = lane & 3;
    const int wm   = warp >> 1;
    const int wn   = warp & 1;

    const int bm = blockIdx.y * BM;
    const int bn = blockIdx.x * BN;

    const uint32_t smBase = (uint32_t)__cvta_generic_to_shared(smh);
    const int rowA0 = wm * 32 + (lane & 15);
    const int koffA = (lane >> 4) << 3;
    const int rowB0 = wn * 64 + (lane & 7) + ((lane >> 4) << 3);
    const int koffB = ((lane >> 3) & 1) << 3;

    float acc[2][8][4];
    #pragma unroll
    for (int i = 0; i < 2; i++)
        #pragma unroll
        for (int j = 0; j < 8; j++)
            #pragma unroll
            for (int l = 0; l < 4; l++) acc[i][j][l] = 0.f;

    const int ntiles = K / BK;

    #define ISSUE_TILE(t, buf) do {                                            \
        __half* As_ = smh + (buf) * STAGE_HALVES;                               \
        __half* Bs_ = As_ + BM * HSTRIDE;                                       \
        int k0_ = (t) * BK;                                                     \
        _Pragma("unroll")                                                       \
        for (int u = 0; u < 4; u++) {                                           \
            int i = tid + u * 256;                                              \
            int r = i >> 3, c = i & 7;                                          \
            cp16(&As_[r * HSTRIDE + c * 8],                                     \
                 &A[(size_t)(bm + r) * K + k0_ + c * 8]);                       \
        }                                                                       \
        _Pragma("unroll")                                                       \
        for (int u = 0; u < 4; u++) {                                           \
            int i = tid + u * 256;                                              \
            int r = i >> 3, c = i & 7;                                          \
            cp16(&Bs_[r * HSTRIDE + c * 8],                                     \
                 &Bt[(size_t)(bn + r) * K + k0_ + c * 8]);                      \
        }                                                                       \
        asm volatile("cp.async.commit_group;");                                 \
    } while (0)

    ISSUE_TILE(0, 0);
    if (ntiles > 1) ISSUE_TILE(1, 1);

    int buf = 0;
    for (int t = 0; t < ntiles; t++) {
        if (t + 1 < ntiles) asm volatile("cp.async.wait_group 1;");
        else                asm volatile("cp.async.wait_group 0;");
        __syncthreads();

        if (t + 2 < ntiles) {
            int nb = buf + 2; if (nb >= NSTAGE) nb -= NSTAGE;
            ISSUE_TILE(t + 2, nb);
        }

        const uint32_t aBase = smBase + buf * STAGE_BYTES;
        const uint32_t bBase = aBase + BM * HSTRIDE * 2;

        #pragma unroll
        for (int ks = 0; ks < 4; ks++) {
            uint32_t af[2][4], bf[8][2];
            #pragma unroll
            for (int mt = 0; mt < 2; mt++) {
                ldsm_x4(af[mt],
                        aBase + ((rowA0 + mt * 16) * HSTRIDE + ks * 16 + koffA) * 2);
            }
            #pragma unroll
            for (int ntp = 0; ntp < 4; ntp++) {
                uint32_t r[4];
                ldsm_x4(r, bBase + ((rowB0 + ntp * 16) * HSTRIDE + ks * 16 + koffB) * 2);
                bf[2 * ntp][0]     = r[0];
                bf[2 * ntp][1]     = r[1];
                bf[2 * ntp + 1][0] = r[2];
                bf[2 * ntp + 1][1] = r[3];
            }
            #pragma unroll
            for (int mt = 0; mt < 2; mt++)
                #pragma unroll
                for (int nt = 0; nt < 8; nt++)
                    mma_f16(acc[mt][nt], af[mt], bf[nt]);
        }

        buf++; if (buf >= NSTAGE) buf = 0;
    }

    if (mode == 3) {
        // fused gelu(gate)*up: nt even = gate, nt odd = up (same original cols)
        __half* Ch = (__half*)Cv;
        #pragma unroll
        for (int mt = 0; mt < 2; mt++) {
            #pragma unroll
            for (int ntp = 0; ntp < 4; ntp++) {
                int m0 = bm + wm * 32 + mt * 16 + gid;
                int oc = (bn >> 1) + wn * 32 + ntp * 8 + tg * 2;
                float* g = acc[mt][2 * ntp];
                float* u = acc[mt][2 * ntp + 1];
                *(__half2*)&Ch[(size_t)m0 * DI_ + oc] =
                    __floats2half2_rn(gelu_t(g[0]) * u[0], gelu_t(g[1]) * u[1]);
                *(__half2*)&Ch[(size_t)(m0 + 8) * DI_ + oc] =
                    __floats2half2_rn(gelu_t(g[2]) * u[2], gelu_t(g[3]) * u[3]);
            }
        }
        return;
    }

    #pragma unroll
    for (int mt = 0; mt < 2; mt++) {
        #pragma unroll
        for (int nt = 0; nt < 8; nt++) {
            int m0 = bm + wm * 32 + mt * 16 + gid;
            int n0 = bn + wn * 64 + nt * 8 + tg * 2;
            float2 v0 = make_float2(acc[mt][nt][0], acc[mt][nt][1]);
            float2 v1 = make_float2(acc[mt][nt][2], acc[mt][nt][3]);
            if (mode == 1) {
                float2 r0 = *(const float2*)&Res[(size_t)m0 * N + n0];
                float2 r1 = *(const float2*)&Res[(size_t)(m0 + 8) * N + n0];
                v0.x += r0.x; v0.y += r0.y;
                v1.x += r1.x; v1.y += r1.y;
            }
            float* C = (float*)Cv;
            *(float2*)&C[(size_t)m0 * N + n0] = v0;
            *(float2*)&C[(size_t)(m0 + 8) * N + n0] = v1;
        }
    }
}

// =================== tensor-core sliding-window attention (R11-13) ====
#define QT 64
#define KT 192
#define KTP 72
#define VTP 200
#define ATTN_SMEM_BYTES ((QT * KTP + KT * KTP + DH_ * VTP) * 2 + KT * 4)

__device__ __forceinline__ void rope_h(const float2* __restrict__ tab, int s, int c,
                                       float4 lo, float4 hi, __half2 olo[2], __half2 ohi[2]) {
    float rlo[4], rhi[4];
    #pragma unroll
    for (int l = 0; l < 4; l++) {
        float2 cs = tab[s * 32 + c * 4 + l];
        float x1 = (&lo.x)[l];
        float x2 = (&hi.x)[l];
        rlo[l] = x1 * cs.x - x2 * cs.y;
        rhi[l] = x2 * cs.x + x1 * cs.y;
    }
    olo[0] = __floats2half2_rn(rlo[0], rlo[1]);
    olo[1] = __floats2half2_rn(rlo[2], rlo[3]);
    ohi[0] = __floats2half2_rn(rhi[0], rhi[1]);
    ohi[1] = __floats2half2_rn(rhi[2], rhi[3]);
}

__global__ __launch_bounds__(128)
void attn_mma_kernel(const float* __restrict__ qkv, const int* __restrict__ pmask,
                     const float2* __restrict__ ropeT, __half* __restrict__ out) {
    extern __shared__ __half smh[];
    __half* Qh = smh;
    __half* Kh = Qh + QT * KTP;
    __half* Vt = Kh + KT * KTP;
    float*  pm = (float*)(Vt + DH_ * VTP);

    const int qt0 = blockIdx.x * QT;
    const int h   = blockIdx.y;
    const int b   = blockIdx.z;
    const int tid = threadIdx.x;
    const int lane = tid & 31;
    const int warp = tid >> 5;
    const int gid  = lane >> 2;
    const int tg   = lane & 3;

    for (int i = tid; i < KT; i += 128) {
        int j = qt0 - WIN + i;
        pm[i] = (j < 0 || j >= S_) ? -1e30f : (pmask[b * S_ + j] ? 0.f : -10000.0f);
    }
    #pragma unroll
    for (int it = 0; it < 4; it++) {
        int i = tid + it * 128;
        int r = i >> 3, c = i & 7;
        int s = qt0 + r;
        size_t base = (size_t)(b * S_ + s) * DQKV + h * DH_;
        float4 lo = *(const float4*)&qkv[base + c * 4];
        float4 hi = *(const float4*)&qkv[base + 32 + c * 4];
        __half2 olo[2], ohi[2];
        rope_h(ropeT, s, c, lo, hi, olo, ohi);
        *(__half2*)&Qh[r * KTP + c * 4]      = olo[0];
        *(__half2*)&Qh[r * KTP + c * 4 + 2]  = olo[1];
        *(__half2*)&Qh[r * KTP + 32 + c * 4]     = ohi[0];
        *(__half2*)&Qh[r * KTP + 32 + c * 4 + 2] = ohi[1];
    }
    #pragma unroll
    for (int it = 0; it < 12; it++) {
        int i = tid + it * 128;
        int r = i >> 3, c = i & 7;
        int j = qt0 - WIN + r;
        __half2 olo[2], ohi[2];
        if (j >= 0 && j < S_) {
            size_t base = (size_t)(b * S_ + j) * DQKV + DM_ + h * DH_;
            float4 lo = *(const float4*)&qkv[base + c * 4];
            float4 hi = *(const float4*)&qkv[base + 32 + c * 4];
            rope_h(ropeT, j, c, lo, hi, olo, ohi);
        } else {
            olo[0] = olo[1] = ohi[0] = ohi[1] = __floats2half2_rn(0.f, 0.f);
        }
        *(__half2*)&Kh[r * KTP + c * 4]      = olo[0];
        *(__half2*)&Kh[r * KTP + c * 4 + 2]  = olo[1];
        *(__half2*)&Kh[r * KTP + 32 + c * 4]     = ohi[0];
        *(__half2*)&Kh[r * KTP + 32 + c * 4 + 2] = ohi[1];
    }
    #pragma unroll
    for (int it = 0; it < 24; it++) {
        int i = tid + it * 128;
        int r = i >> 4, c = i & 15;
        int j = qt0 - WIN + r;
        float4 v = make_float4(0.f, 0.f, 0.f, 0.f);
        if (j >= 0 && j < S_)
            v = *(const float4*)&qkv[(size_t)(b * S_ + j) * DQKV + 2 * DM_ + h * DH_ + c * 4];
        Vt[(c * 4 + 0) * VTP + r] = __float2half_rn(v.x);
        Vt[(c * 4 + 1) * VTP + r] = __float2half_rn(v.y);
        Vt[(c * 4 + 2) * VTP + r] = __float2half_rn(v.z);
        Vt[(c * 4 + 3) * VTP + r] = __float2half_rn(v.w);
    }
    __syncthreads();

    const int rq = warp * 16;
    float acc[24][4];
    #pragma unroll
    for (int nt = 0; nt < 24; nt++)
        #pragma unroll
        for (int e = 0; e < 4; e++) acc[nt][e] = 0.f;

    #pragma unroll
    for (int ks = 0; ks < 4; ks++) {
        const int kb = ks * 16 + 2 * tg;
        uint32_t a[4];
        a[0] = *(const uint32_t*)&Qh[(rq + gid) * KTP + kb];
        a[1] = *(const uint32_t*)&Qh[(rq + gid + 8) * KTP + kb];
        a[2] = *(const uint32_t*)&Qh[(rq + gid) * KTP + kb + 8];
        a[3] = *(const uint32_t*)&Qh[(rq + gid + 8) * KTP + kb + 8];
        #pragma unroll
        for (int nt = 0; nt < 24; nt++) {
            int n = nt * 8 + gid;
            uint32_t bfr[2];
            bfr[0] = *(const uint32_t*)&Kh[n * KTP + kb];
            bfr[1] = *(const uint32_t*)&Kh[n * KTP + kb + 8];
            mma_f16(acc[nt], a, bfr);
        }
    }

    const int ql0 = rq + gid;
    float m0 = -1e30f, m1 = -1e30f;
    #pragma unroll
    for (int nt = 0; nt < 24; nt++) {
        #pragma unroll
        for (int e = 0; e < 4; e++) {
            int col = nt * 8 + 2 * tg + (e & 1);
            int ql  = ql0 + ((e >> 1) << 3);
            float s = acc[nt][e] * 0.125f + pm[col];
            int d = col - ql - WIN;
            if (d > WIN || d < -WIN) s -= 10000.0f;
            acc[nt][e] = s;
            if (e < 2) m0 = fmaxf(m0, s); else m1 = fmaxf(m1, s);
        }
    }
    m0 = fmaxf(m0, __shfl_xor_sync(0xffffffffu, m0, 1));
    m0 = fmaxf(m0, __shfl_xor_sync(0xffffffffu, m0, 2));
    m1 = fmaxf(m1, __shfl_xor_sync(0xffffffffu, m1, 1));
    m1 = fmaxf(m1, __shfl_xor_sync(0xffffffffu, m1, 2));

    float s0 = 0.f, s1 = 0.f;
    #pragma unroll
    for (int nt = 0; nt < 24; nt++) {
        float e0 = expf(acc[nt][0] - m0);
        float e1 = expf(acc[nt][1] - m0);
        float e2 = expf(acc[nt][2] - m1);
        float e3 = expf(acc[nt][3] - m1);
        acc[nt][0] = e0; acc[nt][1] = e1; acc[nt][2] = e2; acc[nt][3] = e3;
        s0 += e0 + e1; s1 += e2 + e3;
    }
    s0 += __shfl_xor_sync(0xffffffffu, s0, 1);
    s0 += __shfl_xor_sync(0xffffffffu, s0, 2);
    s1 += __shfl_xor_sync(0xffffffffu, s1, 1);
    s1 += __shfl_xor_sync(0xffffffffu, s1, 2);
    const float inv0 = 1.0f / s0;
    const float inv1 = 1.0f / s1;

    float accV[8][4];
    #pragma unroll
    for (int nt = 0; nt < 8; nt++)
        #pragma unroll
        for (int e = 0; e < 4; e++) accV[nt][e] = 0.f;

    #pragma unroll
    for (int ks = 0; ks < 12; ks++) {
        uint32_t a[4];
        __half2 h0 = __floats2half2_rn(acc[2 * ks][0] * inv0,     acc[2 * ks][1] * inv0);
        __half2 h1 = __floats2half2_rn(acc[2 * ks][2] * inv1,     acc[2 * ks][3] * inv1);
        __half2 h2 = __floats2half2_rn(acc[2 * ks + 1][0] * inv0, acc[2 * ks + 1][1] * inv0);
        __half2 h3 = __floats2half2_rn(acc[2 * ks + 1][2] * inv1, acc[2 * ks + 1][3] * inv1);
        a[0] = *(uint32_t*)&h0;
        a[1] = *(uint32_t*)&h1;
        a[2] = *(uint32_t*)&h2;
        a[3] = *(uint32_t*)&h3;
        const int kb = ks * 16 + 2 * tg;
        #pragma unroll
        for (int nt = 0; nt < 8; nt++) {
            int n = nt * 8 + gid;
            uint32_t bfr[2];
            bfr[0] = *(const uint32_t*)&Vt[n * VTP + kb];
            bfr[1] = *(const uint32_t*)&Vt[n * VTP + kb + 8];
            mma_f16(accV[nt], a, bfr);
        }
    }

    #pragma unroll
    for (int nt = 0; nt < 8; nt++) {
        int col = h * DH_ + nt * 8 + 2 * tg;
        size_t r0 = (size_t)(b * S_ + qt0 + ql0) * DM_ + col;
        size_t r1 = (size_t)(b * S_ + qt0 + ql0 + 8) * DM_ + col;
        *(__half2*)&out[r0] = __floats2half2_rn(accV[nt][0], accV[nt][1]);
        *(__half2*)&out[r1] = __floats2half2_rn(accV[nt][2], accV[nt][3]);
    }
}

// ---------------- launch ----------------
extern "C" void kernel_launch(void* const* d_in, const int* in_sizes, int n_in,
                              void* d_out, int out_size) {
    const float* x          = (const float*)d_in[0];
    const int*   pmask      = (const int*)  d_in[1];
    const float* w_qkv      = (const float*)d_in[2];
    const float* w_o        = (const float*)d_in[3];
    const float* gamma_attn = (const float*)d_in[4];
    const float* gamma_mlp  = (const float*)d_in[5];
    const float* w_i0       = (const float*)d_in[6];
    const float* w_i1       = (const float*)d_in[7];
    const float* w_mo       = (const float*)d_in[8];
    float* out = (float*)d_out;

    __half *h, *attn, *act, *wqkv, *wo, *wi01, *wmo;
    float *qkv, *x1;
    float2* ropeT;
    cudaGetSymbolAddress((void**)&h,    g_h);
    cudaGetSymbolAddress((void**)&qkv,  g_qkv);
    cudaGetSymbolAddress((void**)&attn, g_attn);
    cudaGetSymbolAddress((void**)&x1,   g_x1);
    cudaGetSymbolAddress((void**)&act,  g_act);
    cudaGetSymbolAddress((void**)&ropeT, g_rope);
    cudaGetSymbolAddress((void**)&wqkv, g_wqkv);
    cudaGetSymbolAddress((void**)&wo,   g_wo);
    cudaGetSymbolAddress((void**)&wi01, g_wi01);
    cudaGetSymbolAddress((void**)&wmo,  g_wmo);

    cudaFuncSetAttribute(mma_gemm_kernel,
                         cudaFuncAttributeMaxDynamicSharedMemorySize, GEMM_SMEM_BYTES);
    cudaFuncSetAttribute(attn_mma_kernel,
                         cudaFuncAttributeMaxDynamicSharedMemorySize, ATTN_SMEM_BYTES);

    wprep_kernel<<<dim3(DI_ / 32, DQKV / 32, 5), dim3(32, 8)>>>(
        w_qkv, w_o, w_i0, w_i1, w_mo, wqkv, wo, wi01, wmo);
    ropetab_kernel<<<(S_ * 32 + 255) / 256, 256>>>(ropeT);

    rmsnorm_kernel<<<ROWS, 256>>>(x, gamma_attn, h);
    mma_gemm_kernel<<<dim3(DQKV / BN, ROWS / BM), 256, GEMM_SMEM_BYTES>>>(
        h, wqkv, nullptr, qkv, ROWS, DQKV, DM_, 0);
    attn_mma_kernel<<<dim3(S_ / QT, H_, B_), 128, ATTN_SMEM_BYTES>>>(qkv, pmask, ropeT, attn);
    mma_gemm_kernel<<<dim3(DM_ / BN, ROWS / BM), 256, GEMM_SMEM_BYTES>>>(
        attn, wo, x, x1, ROWS, DM_, DM_, 1);
    rmsnorm_kernel<<<ROWS, 256>>>(x1, gamma_mlp, h);
    // fused gate/up GEMM: N = 2*DI_ interleaved, epilogue writes act (fp16, DI_ wide)
    mma_gemm_kernel<<<dim3(2 * DI_ / BN, ROWS / BM), 256, GEMM_SMEM_BYTES>>>(
        h, wi01, nullptr, act, ROWS, 2 * DI_, DM_, 3);
    mma_gemm_kernel<<<dim3(DM_ / BN, ROWS / BM), 256, GEMM_SMEM_BYTES>>>(
        act, wmo, x1, out, ROWS, DM_, DI_, 1);
}